// round 4
// baseline (speedup 1.0000x reference)
#include <cuda_runtime.h>
#include <math.h>

#define N_NODES 10000
#define N_EDGES 100000

// irreps dims: node = 64x0e + 32x1o, edge = 8x0e + 8x1o, hidden = 96x0e + 32x1o
// normalization constants
#define INV_SQRT3    0.57735026918962576f
#define NORM_MSG     0.036084391824351614f   // 1/sqrt(768)
#define NORM_UPD_S   0.011811391307201575f   // 1/sqrt(7168)
#define NORM_UPD_V   0.013975424859373686f   // 1/sqrt(5120)
#define NORM_LIN64   0.125f                  // 1/sqrt(64)
#define NORM_LIN32   0.17677669529663687f    // 1/sqrt(32)

// scratch: aggregated messages per node: [96 scalars | 32x3 vectors] = 192 floats
__device__ float g_agg[N_NODES * 192];

__global__ void zero_agg_kernel() {
    int i = blockIdx.x * blockDim.x + threadIdx.x;
    if (i < N_NODES * 192) g_agg[i] = 0.f;
}

// ============================================================================
// EDGE KERNEL: 32 edges / block, 128 threads.
// Stage 1:  ms[32e][96w] = A_s[32e][768k] @ Bs[768k][96w]   (k = u*8+v coeffs)
// Stage 2:  mv[96r][32w] = A_v[96r][768k] @ Bv[768k][32w]   (r = m*32+e)
// Epilogue: gate (silu / sigmoid), equivariant linear, atomic scatter to g_agg
// ============================================================================
#define TE 32
#define EDGE_SMEM_BYTES ((18432 + 64) * 4)

__global__ void __launch_bounds__(128) edge_kernel(
    const float* __restrict__ nf, const float* __restrict__ ea,
    const float* __restrict__ Wss, const float* __restrict__ Wvv,
    const float* __restrict__ Wsv, const float* __restrict__ Wvs,
    const float* __restrict__ WLs, const float* __restrict__ WLv,
    const int* __restrict__ eidx)
{
    extern __shared__ float sm[];
    float* s_xs = sm;            // 2048  [e][u<64]
    float* s_xv = sm + 2048;     // 3072  [e][u*3+m]
    float* s_ys = sm + 5120;     // 256   [e][v<8]
    float* s_yv = sm + 5376;     // 768   [e][v*3+m]
    float* s_A  = sm + 6144;     // 3072  coefficient chunk
    float* s_B  = sm + 9216;     // 3072  weight chunk
    float* s_ms = sm + 12288;    // 3072  [e][w<96]
    float* s_mv = sm + 15360;    // 3072  [m][e][w<32]
    int*   s_row = (int*)(sm + 18432);   // 32
    int*   s_col = s_row + 32;           // 32

    const int t  = threadIdx.x;
    const int e0 = blockIdx.x * TE;

    if (t < TE) {
        s_row[t] = eidx[e0 + t];
        s_col[t] = eidx[N_EDGES + e0 + t];
    }
    __syncthreads();
    // gather node features (col side) + edge attrs
    for (int i = t; i < TE * 160; i += 128) {
        int e = i / 160, c = i - e * 160;
        float v = nf[(long)s_col[e] * 160 + c];
        if (c < 64) s_xs[e * 64 + c] = v; else s_xv[e * 96 + (c - 64)] = v;
    }
    for (int i = t; i < TE * 32; i += 128) {
        int e = i >> 5, c = i & 31;
        float v = ea[(long)(e0 + e) * 32 + c];
        if (c < 8) s_ys[e * 8 + c] = v; else s_yv[e * 24 + (c - 8)] = v;
    }
    __syncthreads();

    // ---------------- stage 1: scalar outputs, K = 512 + 256 ----------------
    const int tw = t & 15;   // w tile: 6 outputs at tw*6
    const int te = t >> 4;   // e tile: 4 edges at te*4
    float acc[24];
    #pragma unroll
    for (int i = 0; i < 24; i++) acc[i] = 0.f;

    for (int k0 = 0; k0 < 768; k0 += 32) {
        // build coefficient chunk A[kk][e]
        for (int i = t; i < 32 * TE; i += 128) {
            int kk = i >> 5, e = i & 31;
            int k = k0 + kk;
            float a;
            if (k < 512) {
                int u = k >> 3, v = k & 7;
                a = s_xs[e * 64 + u] * s_ys[e * 8 + v];
            } else {
                int k2 = k - 512; int u = k2 >> 3, v = k2 & 7;
                const float* xp = s_xv + e * 96 + u * 3;
                const float* yp = s_yv + e * 24 + v * 3;
                a = INV_SQRT3 * (xp[0] * yp[0] + xp[1] * yp[1] + xp[2] * yp[2]);
            }
            s_A[kk * 32 + e] = a;
        }
        // load weight chunk B[kk][w]
        for (int i = t; i < 32 * 96; i += 128) {
            int kk = i / 96, w = i - kk * 96;
            int k = k0 + kk;
            s_B[i] = (k < 512) ? Wss[k * 96 + w] : Wvv[(k - 512) * 96 + w];
        }
        __syncthreads();
        #pragma unroll 8
        for (int kk = 0; kk < 32; kk++) {
            float av[4], bv[6];
            #pragma unroll
            for (int i = 0; i < 4; i++) av[i] = s_A[kk * 32 + te * 4 + i];
            #pragma unroll
            for (int j = 0; j < 6; j++) bv[j] = s_B[kk * 96 + tw * 6 + j];
            #pragma unroll
            for (int i = 0; i < 4; i++)
                #pragma unroll
                for (int j = 0; j < 6; j++)
                    acc[i * 6 + j] = fmaf(av[i], bv[j], acc[i * 6 + j]);
        }
        __syncthreads();
    }
    #pragma unroll
    for (int i = 0; i < 4; i++)
        #pragma unroll
        for (int j = 0; j < 6; j++)
            s_ms[(te * 4 + i) * 96 + tw * 6 + j] = acc[i * 6 + j] * NORM_MSG;

    // ---------------- stage 2: vector outputs, rows r=m*32+e -----------------
    const int tw2 = t & 7;   // w tile: 4 outputs at tw2*4
    const int tr  = t >> 3;  // row tile: 6 rows at tr*6
    #pragma unroll
    for (int i = 0; i < 24; i++) acc[i] = 0.f;

    for (int k0 = 0; k0 < 768; k0 += 32) {
        for (int i = t; i < 32 * 96; i += 128) {
            int kk = i / 96, r = i - kk * 96;
            int m = r >> 5, e = r & 31;
            int k = k0 + kk;
            float a;
            if (k < 512) {
                int u = k >> 3, v = k & 7;
                a = s_xs[e * 64 + u] * s_yv[e * 24 + v * 3 + m];
            } else {
                int k2 = k - 512; int u = k2 >> 3, v = k2 & 7;
                a = s_xv[e * 96 + u * 3 + m] * s_ys[e * 8 + v];
            }
            s_A[i] = a;
        }
        for (int i = t; i < 32 * 32; i += 128) {
            int kk = i >> 5, w = i & 31;
            int k = k0 + kk;
            s_B[i] = (k < 512) ? Wsv[k * 32 + w] : Wvs[(k - 512) * 32 + w];
        }
        __syncthreads();
        #pragma unroll 8
        for (int kk = 0; kk < 32; kk++) {
            float av2[6], bv2[4];
            #pragma unroll
            for (int i = 0; i < 6; i++) av2[i] = s_A[kk * 96 + tr * 6 + i];
            #pragma unroll
            for (int j = 0; j < 4; j++) bv2[j] = s_B[kk * 32 + tw2 * 4 + j];
            #pragma unroll
            for (int i = 0; i < 6; i++)
                #pragma unroll
                for (int j = 0; j < 4; j++)
                    acc[i * 4 + j] = fmaf(av2[i], bv2[j], acc[i * 4 + j]);
        }
        __syncthreads();
    }
    #pragma unroll
    for (int i = 0; i < 6; i++)
        #pragma unroll
        for (int j = 0; j < 4; j++)
            s_mv[(tr * 6 + i) * 32 + tw2 * 4 + j] = acc[i * 4 + j] * NORM_MSG;

    __syncthreads();

    // ---------------- epilogue: gate + linear + atomic scatter ----------------
    float* s_WLs = s_A;   // 6144 floats (A+B regions, contiguous, now dead)
    float* s_WLv = s_ys;  // 1024 floats (ys+yv regions, now dead)
    for (int i = t; i < 6144; i += 128) s_WLs[i] = WLs[i];
    for (int i = t; i < 1024; i += 128) s_WLv[i] = WLv[i];
    // silu plain scalars in place (gate part [64:96) stays raw)
    for (int i = t; i < TE * 64; i += 128) {
        int e = i >> 6, u = i & 63;
        float x = s_ms[e * 96 + u];
        s_ms[e * 96 + u] = x / (1.f + expf(-x));
    }
    // sigmoid gates applied to vectors
    for (int i = t; i < 3 * TE * 32; i += 128) {
        int r = i >> 5, u = i & 31;
        int e = r & 31;
        float g = 1.f / (1.f + expf(-s_ms[e * 96 + 64 + u]));
        s_mv[i] *= g;
    }
    __syncthreads();

    // ls[e][w<96] = plain @ WLs / 8, scatter to agg_s
    for (int i = t; i < TE * 96; i += 128) {
        int e = i / 96, w = i - e * 96;
        float sum = 0.f;
        #pragma unroll
        for (int u = 0; u < 64; u++)
            sum = fmaf(s_ms[e * 96 + u], s_WLs[u * 96 + w], sum);
        atomicAdd(&g_agg[(long)s_row[e] * 192 + w], sum * NORM_LIN64);
    }
    // lv[e][w<32][m] = pv @ WLv / sqrt(32), scatter to agg_v (layout w*3+m)
    for (int i = t; i < TE * 96; i += 128) {
        int e = i / 96, c = i - e * 96;
        int w = c / 3, m = c - w * 3;
        float sum = 0.f;
        #pragma unroll
        for (int u = 0; u < 32; u++)
            sum = fmaf(s_mv[(m * 32 + e) * 32 + u], s_WLv[u * 32 + w], sum);
        atomicAdd(&g_agg[(long)s_row[e] * 192 + 96 + c], sum * NORM_LIN32);
    }
}

// ============================================================================
// NODE KERNEL: 32 nodes / block, 128 threads.
// Stage 1: us[32n][96w], K = 64*96 (xs x agg_s) + 32*32 (xv . agg_v) = 7168
// Stage 2: uv[96r][32w], K = 64*32 (xs x agg_v_m) + 32*96 (xv_m x agg_s) = 5120
// Epilogue: gate, linear, residual, write output
// ============================================================================
#define TN 32
#define NODE_SMEM_BYTES (23552 * 4)

__global__ void __launch_bounds__(128) node_kernel(
    const float* __restrict__ nf,
    const float* __restrict__ Wss, const float* __restrict__ Wvv,
    const float* __restrict__ Wsv, const float* __restrict__ Wvs,
    const float* __restrict__ WLs, const float* __restrict__ WLv,
    float* __restrict__ out)
{
    extern __shared__ float sm[];
    float* s_xs = sm;            // 2048  [e][u<64]
    float* s_xv = sm + 2048;     // 3072  [e][u*3+m]
    float* s_as = sm + 5120;     // 3072  [e][v<96]
    float* s_av = sm + 8192;     // 3072  [e][v*3+m]
    float* s_A  = sm + 11264;    // 3072
    float* s_B  = sm + 14336;    // 3072
    float* s_us = sm + 17408;    // 3072  [e][w<96]
    float* s_uv = sm + 20480;    // 3072  [m][e][w<32]

    const int t  = threadIdx.x;
    const int n0 = blockIdx.x * TN;

    for (int i = t; i < TN * 160; i += 128) {
        int e = i / 160, c = i - e * 160;
        int n = n0 + e;
        float v = (n < N_NODES) ? nf[(long)n * 160 + c] : 0.f;
        if (c < 64) s_xs[e * 64 + c] = v; else s_xv[e * 96 + (c - 64)] = v;
    }
    for (int i = t; i < TN * 192; i += 128) {
        int e = i / 192, c = i - e * 192;
        int n = n0 + e;
        float v = (n < N_NODES) ? g_agg[(long)n * 192 + c] : 0.f;
        if (c < 96) s_as[e * 96 + c] = v; else s_av[e * 96 + (c - 96)] = v;
    }
    __syncthreads();

    // ---------------- stage 1: K = 6144 + 1024 = 7168 ----------------
    const int tw = t & 15, te = t >> 4;
    float acc[24];
    #pragma unroll
    for (int i = 0; i < 24; i++) acc[i] = 0.f;

    for (int k0 = 0; k0 < 7168; k0 += 32) {
        for (int i = t; i < 32 * TN; i += 128) {
            int kk = i >> 5, e = i & 31;
            int k = k0 + kk;
            float a;
            if (k < 6144) {
                int u = k / 96, v = k - u * 96;
                a = s_xs[e * 64 + u] * s_as[e * 96 + v];
            } else {
                int k2 = k - 6144; int u = k2 >> 5, v = k2 & 31;
                const float* xp = s_xv + e * 96 + u * 3;
                const float* yp = s_av + e * 96 + v * 3;
                a = INV_SQRT3 * (xp[0] * yp[0] + xp[1] * yp[1] + xp[2] * yp[2]);
            }
            s_A[kk * 32 + e] = a;
        }
        for (int i = t; i < 32 * 96; i += 128) {
            int kk = i / 96, w = i - kk * 96;
            int k = k0 + kk;
            s_B[i] = (k < 6144) ? Wss[(long)k * 96 + w] : Wvv[(long)(k - 6144) * 96 + w];
        }
        __syncthreads();
        #pragma unroll 8
        for (int kk = 0; kk < 32; kk++) {
            float av[4], bv[6];
            #pragma unroll
            for (int i = 0; i < 4; i++) av[i] = s_A[kk * 32 + te * 4 + i];
            #pragma unroll
            for (int j = 0; j < 6; j++) bv[j] = s_B[kk * 96 + tw * 6 + j];
            #pragma unroll
            for (int i = 0; i < 4; i++)
                #pragma unroll
                for (int j = 0; j < 6; j++)
                    acc[i * 6 + j] = fmaf(av[i], bv[j], acc[i * 6 + j]);
        }
        __syncthreads();
    }
    #pragma unroll
    for (int i = 0; i < 4; i++)
        #pragma unroll
        for (int j = 0; j < 6; j++)
            s_us[(te * 4 + i) * 96 + tw * 6 + j] = acc[i * 6 + j] * NORM_UPD_S;

    // ---------------- stage 2: K = 2048 + 3072 = 5120 ----------------
    const int tw2 = t & 7;
    const int tr  = t >> 3;
    #pragma unroll
    for (int i = 0; i < 24; i++) acc[i] = 0.f;

    for (int k0 = 0; k0 < 5120; k0 += 32) {
        for (int i = t; i < 32 * 96; i += 128) {
            int kk = i / 96, r = i - kk * 96;
            int m = r >> 5, e = r & 31;
            int k = k0 + kk;
            float a;
            if (k < 2048) {
                int u = k >> 5, v = k & 31;
                a = s_xs[e * 64 + u] * s_av[e * 96 + v * 3 + m];
            } else {
                int k2 = k - 2048; int u = k2 / 96, v = k2 - u * 96;
                a = s_xv[e * 96 + u * 3 + m] * s_as[e * 96 + v];
            }
            s_A[i] = a;
        }
        for (int i = t; i < 32 * 32; i += 128) {
            int kk = i >> 5, w = i & 31;
            int k = k0 + kk;
            s_B[i] = (k < 2048) ? Wsv[k * 32 + w] : Wvs[(k - 2048) * 32 + w];
        }
        __syncthreads();
        #pragma unroll 8
        for (int kk = 0; kk < 32; kk++) {
            float av2[6], bv2[4];
            #pragma unroll
            for (int i = 0; i < 6; i++) av2[i] = s_A[kk * 96 + tr * 6 + i];
            #pragma unroll
            for (int j = 0; j < 4; j++) bv2[j] = s_B[kk * 32 + tw2 * 4 + j];
            #pragma unroll
            for (int i = 0; i < 6; i++)
                #pragma unroll
                for (int j = 0; j < 4; j++)
                    acc[i * 4 + j] = fmaf(av2[i], bv2[j], acc[i * 4 + j]);
        }
        __syncthreads();
    }
    #pragma unroll
    for (int i = 0; i < 6; i++)
        #pragma unroll
        for (int j = 0; j < 4; j++)
            s_uv[(tr * 6 + i) * 32 + tw2 * 4 + j] = acc[i * 4 + j] * NORM_UPD_V;

    __syncthreads();

    // ---------------- epilogue: gate + linear + residual ----------------
    float* s_WLs2 = s_A;          // 4096 (A region + start of B, dead)
    float* s_WLv2 = s_A + 4096;   // 1024 (inside B region, dead)
    for (int i = t; i < 4096; i += 128) s_WLs2[i] = WLs[i];
    for (int i = t; i < 1024; i += 128) s_WLv2[i] = WLv[i];
    for (int i = t; i < TN * 64; i += 128) {
        int e = i >> 6, u = i & 63;
        float x = s_us[e * 96 + u];
        s_us[e * 96 + u] = x / (1.f + expf(-x));
    }
    for (int i = t; i < 3 * TN * 32; i += 128) {
        int r = i >> 5, u = i & 31;
        int e = r & 31;
        float g = 1.f / (1.f + expf(-s_us[e * 96 + 64 + u]));
        s_uv[i] *= g;
    }
    __syncthreads();

    // scalar output: out[n][w<64] = ns + (gs @ WLs)/8
    for (int i = t; i < TN * 64; i += 128) {
        int e = i >> 6, w = i & 63;
        int n = n0 + e;
        if (n < N_NODES) {
            float sum = 0.f;
            #pragma unroll
            for (int u = 0; u < 64; u++)
                sum = fmaf(s_us[e * 96 + u], s_WLs2[u * 64 + w], sum);
            out[(long)n * 160 + w] = s_xs[e * 64 + w] + sum * NORM_LIN64;
        }
    }
    // vector output: out[n][64 + w*3+m] = nv + (gv @ WLv)/sqrt(32)
    for (int i = t; i < TN * 96; i += 128) {
        int e = i / 96, c = i - e * 96;
        int w = c / 3, m = c - w * 3;
        int n = n0 + e;
        if (n < N_NODES) {
            float sum = 0.f;
            #pragma unroll
            for (int u = 0; u < 32; u++)
                sum = fmaf(s_uv[(m * 32 + e) * 32 + u], s_WLv2[u * 32 + w], sum);
            out[(long)n * 160 + 64 + c] = s_xv[e * 96 + c] + sum * NORM_LIN32;
        }
    }
}

extern "C" void kernel_launch(void* const* d_in, const int* in_sizes, int n_in,
                              void* d_out, int out_size) {
    const float* nf   = (const float*)d_in[0];
    const float* ea   = (const float*)d_in[1];
    const float* Wmss = (const float*)d_in[2];
    const float* Wmvv = (const float*)d_in[3];
    const float* Wmsv = (const float*)d_in[4];
    const float* Wmvs = (const float*)d_in[5];
    const float* WLms = (const float*)d_in[6];
    const float* WLmv = (const float*)d_in[7];
    const float* Wuss = (const float*)d_in[8];
    const float* Wuvv = (const float*)d_in[9];
    const float* Wusv = (const float*)d_in[10];
    const float* Wuvs = (const float*)d_in[11];
    const float* WLus = (const float*)d_in[12];
    const float* WLuv = (const float*)d_in[13];
    const int*   eidx = (const int*)d_in[14];
    float* out = (float*)d_out;

    cudaFuncSetAttribute(edge_kernel, cudaFuncAttributeMaxDynamicSharedMemorySize,
                         EDGE_SMEM_BYTES);
    cudaFuncSetAttribute(node_kernel, cudaFuncAttributeMaxDynamicSharedMemorySize,
                         NODE_SMEM_BYTES);

    zero_agg_kernel<<<(N_NODES * 192 + 255) / 256, 256>>>();
    edge_kernel<<<N_EDGES / TE, 128, EDGE_SMEM_BYTES>>>(
        nf, ea, Wmss, Wmvv, Wmsv, Wmvs, WLms, WLmv, eidx);
    node_kernel<<<(N_NODES + TN - 1) / TN, 128, NODE_SMEM_BYTES>>>(
        nf, Wuss, Wuvv, Wusv, Wuvs, WLus, WLuv, out);
}

// round 5
// speedup vs baseline: 1.5675x; 1.5675x over previous
#include <cuda_runtime.h>
#include <math.h>

#define N_NODES 10000
#define N_EDGES 100000

// irreps dims: node = 64x0e + 32x1o, edge = 8x0e + 8x1o, hidden = 96x0e + 32x1o
// normalization constants
#define INV_SQRT3    0.57735026918962576f
#define NORM_MSG     0.036084391824351614f   // 1/sqrt(768)
#define NORM_UPD_S   0.011811391307201575f   // 1/sqrt(7168)
#define NORM_UPD_V   0.013975424859373686f   // 1/sqrt(5120)
#define NORM_LIN64   0.125f                  // 1/sqrt(64)
#define NORM_LIN32   0.17677669529663687f    // 1/sqrt(32)

// scratch: aggregated messages per node: [96 scalars | 32x3 vectors] = 192 floats
__device__ float g_agg[N_NODES * 192];

__global__ void zero_agg_kernel() {
    int i = blockIdx.x * blockDim.x + threadIdx.x;
    if (i < N_NODES * 192) g_agg[i] = 0.f;
}

// ============================================================================
// EDGE KERNEL: 32 edges / block, 128 threads.
// Stage 1:  ms[32e][96w] = A_s[32e][768k] @ Bs[768k][96w]   (k = u*8+v coeffs)
// Stage 2:  mv[96r][32w] = A_v[96r][768k] @ Bv[768k][32w]   (r = m*32+e)
// Epilogue: gate (silu / sigmoid), equivariant linear, atomic scatter to g_agg
// ============================================================================
#define TE 32
#define EDGE_SMEM_BYTES ((18432 + 64) * 4)

__global__ void __launch_bounds__(128) edge_kernel(
    const float* __restrict__ nf, const float* __restrict__ ea,
    const float* __restrict__ Wss, const float* __restrict__ Wvv,
    const float* __restrict__ Wsv, const float* __restrict__ Wvs,
    const float* __restrict__ WLs, const float* __restrict__ WLv,
    const int* __restrict__ eidx)
{
    extern __shared__ float sm[];
    float* s_xs = sm;            // 2048  [e][u<64]
    float* s_xv = sm + 2048;     // 3072  [e][u*3+m]
    float* s_ys = sm + 5120;     // 256   [e][v<8]
    float* s_yv = sm + 5376;     // 768   [e][v*3+m]
    float* s_A  = sm + 6144;     // 3072  coefficient chunk
    float* s_B  = sm + 9216;     // 3072  weight chunk
    float* s_ms = sm + 12288;    // 3072  [e][w<96]
    float* s_mv = sm + 15360;    // 3072  [m][e][w<32]
    int*   s_row = (int*)(sm + 18432);   // 32
    int*   s_col = s_row + 32;           // 32

    const int t  = threadIdx.x;
    const int e0 = blockIdx.x * TE;

    if (t < TE) {
        s_row[t] = eidx[e0 + t];
        s_col[t] = eidx[N_EDGES + e0 + t];
    }
    __syncthreads();
    // gather node features (col side) + edge attrs
    for (int i = t; i < TE * 160; i += 128) {
        int e = i / 160, c = i - e * 160;
        float v = nf[(long)s_col[e] * 160 + c];
        if (c < 64) s_xs[e * 64 + c] = v; else s_xv[e * 96 + (c - 64)] = v;
    }
    for (int i = t; i < TE * 32; i += 128) {
        int e = i >> 5, c = i & 31;
        float v = ea[(long)(e0 + e) * 32 + c];
        if (c < 8) s_ys[e * 8 + c] = v; else s_yv[e * 24 + (c - 8)] = v;
    }
    __syncthreads();

    // ---------------- stage 1: scalar outputs, K = 512 + 256 ----------------
    const int tw = t & 15;   // w tile: 6 outputs at tw*6
    const int te = t >> 4;   // e tile: 4 edges at te*4
    float acc[24];
    #pragma unroll
    for (int i = 0; i < 24; i++) acc[i] = 0.f;

    for (int k0 = 0; k0 < 768; k0 += 32) {
        // build coefficient chunk A[kk][e]
        for (int i = t; i < 32 * TE; i += 128) {
            int kk = i >> 5, e = i & 31;
            int k = k0 + kk;
            float a;
            if (k < 512) {
                int u = k >> 3, v = k & 7;
                a = s_xs[e * 64 + u] * s_ys[e * 8 + v];
            } else {
                int k2 = k - 512; int u = k2 >> 3, v = k2 & 7;
                const float* xp = s_xv + e * 96 + u * 3;
                const float* yp = s_yv + e * 24 + v * 3;
                a = INV_SQRT3 * (xp[0] * yp[0] + xp[1] * yp[1] + xp[2] * yp[2]);
            }
            s_A[kk * 32 + e] = a;
        }
        // load weight chunk B[kk][w]
        for (int i = t; i < 32 * 96; i += 128) {
            int kk = i / 96, w = i - kk * 96;
            int k = k0 + kk;
            s_B[i] = (k < 512) ? Wss[k * 96 + w] : Wvv[(k - 512) * 96 + w];
        }
        __syncthreads();
        #pragma unroll 8
        for (int kk = 0; kk < 32; kk++) {
            float av[4], bv[6];
            #pragma unroll
            for (int i = 0; i < 4; i++) av[i] = s_A[kk * 32 + te * 4 + i];
            #pragma unroll
            for (int j = 0; j < 6; j++) bv[j] = s_B[kk * 96 + tw * 6 + j];
            #pragma unroll
            for (int i = 0; i < 4; i++)
                #pragma unroll
                for (int j = 0; j < 6; j++)
                    acc[i * 6 + j] = fmaf(av[i], bv[j], acc[i * 6 + j]);
        }
        __syncthreads();
    }
    #pragma unroll
    for (int i = 0; i < 4; i++)
        #pragma unroll
        for (int j = 0; j < 6; j++)
            s_ms[(te * 4 + i) * 96 + tw * 6 + j] = acc[i * 6 + j] * NORM_MSG;

    // ---------------- stage 2: vector outputs, rows r=m*32+e -----------------
    const int tw2 = t & 7;   // w tile: 4 outputs at tw2*4
    const int tr  = t >> 3;  // row tile: 6 rows at tr*6
    #pragma unroll
    for (int i = 0; i < 24; i++) acc[i] = 0.f;

    for (int k0 = 0; k0 < 768; k0 += 32) {
        for (int i = t; i < 32 * 96; i += 128) {
            int kk = i / 96, r = i - kk * 96;
            int m = r >> 5, e = r & 31;
            int k = k0 + kk;
            float a;
            if (k < 512) {
                int u = k >> 3, v = k & 7;
                a = s_xs[e * 64 + u] * s_yv[e * 24 + v * 3 + m];
            } else {
                int k2 = k - 512; int u = k2 >> 3, v = k2 & 7;
                a = s_xv[e * 96 + u * 3 + m] * s_ys[e * 8 + v];
            }
            s_A[i] = a;
        }
        for (int i = t; i < 32 * 32; i += 128) {
            int kk = i >> 5, w = i & 31;
            int k = k0 + kk;
            s_B[i] = (k < 512) ? Wsv[k * 32 + w] : Wvs[(k - 512) * 32 + w];
        }
        __syncthreads();
        #pragma unroll 8
        for (int kk = 0; kk < 32; kk++) {
            float av2[6], bv2[4];
            #pragma unroll
            for (int i = 0; i < 6; i++) av2[i] = s_A[kk * 96 + tr * 6 + i];
            #pragma unroll
            for (int j = 0; j < 4; j++) bv2[j] = s_B[kk * 32 + tw2 * 4 + j];
            #pragma unroll
            for (int i = 0; i < 6; i++)
                #pragma unroll
                for (int j = 0; j < 4; j++)
                    acc[i * 4 + j] = fmaf(av2[i], bv2[j], acc[i * 4 + j]);
        }
        __syncthreads();
    }
    #pragma unroll
    for (int i = 0; i < 6; i++)
        #pragma unroll
        for (int j = 0; j < 4; j++)
            s_mv[(tr * 6 + i) * 32 + tw2 * 4 + j] = acc[i * 4 + j] * NORM_MSG;

    __syncthreads();

    // ---------------- epilogue: gate + linear + atomic scatter ----------------
    float* s_WLs = s_A;   // 6144 floats (A+B regions, contiguous, now dead)
    float* s_WLv = s_ys;  // 1024 floats (ys+yv regions, now dead)
    for (int i = t; i < 6144; i += 128) s_WLs[i] = WLs[i];
    for (int i = t; i < 1024; i += 128) s_WLv[i] = WLv[i];
    // silu plain scalars in place (gate part [64:96) stays raw)
    for (int i = t; i < TE * 64; i += 128) {
        int e = i >> 6, u = i & 63;
        float x = s_ms[e * 96 + u];
        s_ms[e * 96 + u] = x / (1.f + expf(-x));
    }
    // sigmoid gates applied to vectors
    for (int i = t; i < 3 * TE * 32; i += 128) {
        int r = i >> 5, u = i & 31;
        int e = r & 31;
        float g = 1.f / (1.f + expf(-s_ms[e * 96 + 64 + u]));
        s_mv[i] *= g;
    }
    __syncthreads();

    // ls[e][w<96] = plain @ WLs / 8, scatter to agg_s
    for (int i = t; i < TE * 96; i += 128) {
        int e = i / 96, w = i - e * 96;
        float sum = 0.f;
        #pragma unroll
        for (int u = 0; u < 64; u++)
            sum = fmaf(s_ms[e * 96 + u], s_WLs[u * 96 + w], sum);
        atomicAdd(&g_agg[(long)s_row[e] * 192 + w], sum * NORM_LIN64);
    }
    // lv[e][w<32][m] = pv @ WLv / sqrt(32), scatter to agg_v (layout w*3+m)
    for (int i = t; i < TE * 96; i += 128) {
        int e = i / 96, c = i - e * 96;
        int w = c / 3, m = c - w * 3;
        float sum = 0.f;
        #pragma unroll
        for (int u = 0; u < 32; u++)
            sum = fmaf(s_mv[(m * 32 + e) * 32 + u], s_WLv[u * 32 + w], sum);
        atomicAdd(&g_agg[(long)s_row[e] * 192 + 96 + c], sum * NORM_LIN32);
    }
}

// ============================================================================
// NODE KERNEL: 32 nodes / block, 128 threads.
// Stage 1: us[32n][96w], K = 64*96 (xs x agg_s) + 32*32 (xv . agg_v) = 7168
// Stage 2: uv[96r][32w], K = 64*32 (xs x agg_v_m) + 32*96 (xv_m x agg_s) = 5120
// Epilogue: gate, linear, residual, write output
// ============================================================================
#define TN 32
#define NODE_SMEM_BYTES (23552 * 4)

__global__ void __launch_bounds__(128) node_kernel(
    const float* __restrict__ nf,
    const float* __restrict__ Wss, const float* __restrict__ Wvv,
    const float* __restrict__ Wsv, const float* __restrict__ Wvs,
    const float* __restrict__ WLs, const float* __restrict__ WLv,
    float* __restrict__ out)
{
    extern __shared__ float sm[];
    float* s_xs = sm;            // 2048  [e][u<64]
    float* s_xv = sm + 2048;     // 3072  [e][u*3+m]
    float* s_as = sm + 5120;     // 3072  [e][v<96]
    float* s_av = sm + 8192;     // 3072  [e][v*3+m]
    float* s_A  = sm + 11264;    // 3072
    float* s_B  = sm + 14336;    // 3072
    float* s_us = sm + 17408;    // 3072  [e][w<96]
    float* s_uv = sm + 20480;    // 3072  [m][e][w<32]

    const int t  = threadIdx.x;
    const int n0 = blockIdx.x * TN;

    for (int i = t; i < TN * 160; i += 128) {
        int e = i / 160, c = i - e * 160;
        int n = n0 + e;
        float v = (n < N_NODES) ? nf[(long)n * 160 + c] : 0.f;
        if (c < 64) s_xs[e * 64 + c] = v; else s_xv[e * 96 + (c - 64)] = v;
    }
    for (int i = t; i < TN * 192; i += 128) {
        int e = i / 192, c = i - e * 192;
        int n = n0 + e;
        float v = (n < N_NODES) ? g_agg[(long)n * 192 + c] : 0.f;
        if (c < 96) s_as[e * 96 + c] = v; else s_av[e * 96 + (c - 96)] = v;
    }
    __syncthreads();

    // ---------------- stage 1: K = 6144 + 1024 = 7168 ----------------
    const int tw = t & 15, te = t >> 4;
    float acc[24];
    #pragma unroll
    for (int i = 0; i < 24; i++) acc[i] = 0.f;

    for (int k0 = 0; k0 < 7168; k0 += 32) {
        for (int i = t; i < 32 * TN; i += 128) {
            int kk = i >> 5, e = i & 31;
            int k = k0 + kk;
            float a;
            if (k < 6144) {
                int u = k / 96, v = k - u * 96;
                a = s_xs[e * 64 + u] * s_as[e * 96 + v];
            } else {
                int k2 = k - 6144; int u = k2 >> 5, v = k2 & 31;
                const float* xp = s_xv + e * 96 + u * 3;
                const float* yp = s_av + e * 96 + v * 3;
                a = INV_SQRT3 * (xp[0] * yp[0] + xp[1] * yp[1] + xp[2] * yp[2]);
            }
            s_A[kk * 32 + e] = a;
        }
        for (int i = t; i < 32 * 96; i += 128) {
            int kk = i / 96, w = i - kk * 96;
            int k = k0 + kk;
            s_B[i] = (k < 6144) ? Wss[(long)k * 96 + w] : Wvv[(long)(k - 6144) * 96 + w];
        }
        __syncthreads();
        #pragma unroll 8
        for (int kk = 0; kk < 32; kk++) {
            float av[4], bv[6];
            #pragma unroll
            for (int i = 0; i < 4; i++) av[i] = s_A[kk * 32 + te * 4 + i];
            #pragma unroll
            for (int j = 0; j < 6; j++) bv[j] = s_B[kk * 96 + tw * 6 + j];
            #pragma unroll
            for (int i = 0; i < 4; i++)
                #pragma unroll
                for (int j = 0; j < 6; j++)
                    acc[i * 6 + j] = fmaf(av[i], bv[j], acc[i * 6 + j]);
        }
        __syncthreads();
    }
    #pragma unroll
    for (int i = 0; i < 4; i++)
        #pragma unroll
        for (int j = 0; j < 6; j++)
            s_us[(te * 4 + i) * 96 + tw * 6 + j] = acc[i * 6 + j] * NORM_UPD_S;

    // ---------------- stage 2: K = 2048 + 3072 = 5120 ----------------
    const int tw2 = t & 7;
    const int tr  = t >> 3;
    #pragma unroll
    for (int i = 0; i < 24; i++) acc[i] = 0.f;

    for (int k0 = 0; k0 < 5120; k0 += 32) {
        for (int i = t; i < 32 * 96; i += 128) {
            int kk = i / 96, r = i - kk * 96;
            int m = r >> 5, e = r & 31;
            int k = k0 + kk;
            float a;
            if (k < 2048) {
                int u = k >> 5, v = k & 31;
                a = s_xs[e * 64 + u] * s_av[e * 96 + v * 3 + m];
            } else {
                int k2 = k - 2048; int u = k2 / 96, v = k2 - u * 96;
                a = s_xv[e * 96 + u * 3 + m] * s_as[e * 96 + v];
            }
            s_A[i] = a;
        }
        for (int i = t; i < 32 * 32; i += 128) {
            int kk = i >> 5, w = i & 31;
            int k = k0 + kk;
            s_B[i] = (k < 2048) ? Wsv[k * 32 + w] : Wvs[(k - 2048) * 32 + w];
        }
        __syncthreads();
        #pragma unroll 8
        for (int kk = 0; kk < 32; kk++) {
            float av2[6], bv2[4];
            #pragma unroll
            for (int i = 0; i < 6; i++) av2[i] = s_A[kk * 96 + tr * 6 + i];
            #pragma unroll
            for (int j = 0; j < 4; j++) bv2[j] = s_B[kk * 32 + tw2 * 4 + j];
            #pragma unroll
            for (int i = 0; i < 6; i++)
                #pragma unroll
                for (int j = 0; j < 4; j++)
                    acc[i * 4 + j] = fmaf(av2[i], bv2[j], acc[i * 4 + j]);
        }
        __syncthreads();
    }
    #pragma unroll
    for (int i = 0; i < 6; i++)
        #pragma unroll
        for (int j = 0; j < 4; j++)
            s_uv[(tr * 6 + i) * 32 + tw2 * 4 + j] = acc[i * 4 + j] * NORM_UPD_V;

    __syncthreads();

    // ---------------- epilogue: gate + linear + residual ----------------
    float* s_WLs2 = s_A;          // 4096 (A region + start of B, dead)
    float* s_WLv2 = s_A + 4096;   // 1024 (inside B region, dead)
    for (int i = t; i < 4096; i += 128) s_WLs2[i] = WLs[i];
    for (int i = t; i < 1024; i += 128) s_WLv2[i] = WLv[i];
    for (int i = t; i < TN * 64; i += 128) {
        int e = i >> 6, u = i & 63;
        float x = s_us[e * 96 + u];
        s_us[e * 96 + u] = x / (1.f + expf(-x));
    }
    for (int i = t; i < 3 * TN * 32; i += 128) {
        int r = i >> 5, u = i & 31;
        int e = r & 31;
        float g = 1.f / (1.f + expf(-s_us[e * 96 + 64 + u]));
        s_uv[i] *= g;
    }
    __syncthreads();

    // scalar output: out[n][w<64] = ns + (gs @ WLs)/8
    for (int i = t; i < TN * 64; i += 128) {
        int e = i >> 6, w = i & 63;
        int n = n0 + e;
        if (n < N_NODES) {
            float sum = 0.f;
            #pragma unroll
            for (int u = 0; u < 64; u++)
                sum = fmaf(s_us[e * 96 + u], s_WLs2[u * 64 + w], sum);
            out[(long)n * 160 + w] = s_xs[e * 64 + w] + sum * NORM_LIN64;
        }
    }
    // vector output: out[n][64 + w*3+m] = nv + (gv @ WLv)/sqrt(32)
    for (int i = t; i < TN * 96; i += 128) {
        int e = i / 96, c = i - e * 96;
        int w = c / 3, m = c - w * 3;
        int n = n0 + e;
        if (n < N_NODES) {
            float sum = 0.f;
            #pragma unroll
            for (int u = 0; u < 32; u++)
                sum = fmaf(s_uv[(m * 32 + e) * 32 + u], s_WLv2[u * 32 + w], sum);
            out[(long)n * 160 + 64 + c] = s_xv[e * 96 + c] + sum * NORM_LIN32;
        }
    }
}

extern "C" void kernel_launch(void* const* d_in, const int* in_sizes, int n_in,
                              void* d_out, int out_size) {
    const float* nf   = (const float*)d_in[0];
    const float* ea   = (const float*)d_in[1];
    const float* Wmss = (const float*)d_in[2];
    const float* Wmvv = (const float*)d_in[3];
    const float* Wmsv = (const float*)d_in[4];
    const float* Wmvs = (const float*)d_in[5];
    const float* WLms = (const float*)d_in[6];
    const float* WLmv = (const float*)d_in[7];
    const float* Wuss = (const float*)d_in[8];
    const float* Wuvv = (const float*)d_in[9];
    const float* Wusv = (const float*)d_in[10];
    const float* Wuvs = (const float*)d_in[11];
    const float* WLus = (const float*)d_in[12];
    const float* WLuv = (const float*)d_in[13];
    const int*   eidx = (const int*)d_in[14];
    float* out = (float*)d_out;

    cudaFuncSetAttribute(edge_kernel, cudaFuncAttributeMaxDynamicSharedMemorySize,
                         EDGE_SMEM_BYTES);
    cudaFuncSetAttribute(node_kernel, cudaFuncAttributeMaxDynamicSharedMemorySize,
                         NODE_SMEM_BYTES);

    zero_agg_kernel<<<(N_NODES * 192 + 255) / 256, 256>>>();
    edge_kernel<<<N_EDGES / TE, 128, EDGE_SMEM_BYTES>>>(
        nf, ea, Wmss, Wmvv, Wmsv, Wmvs, WLms, WLmv, eidx);
    node_kernel<<<(N_NODES + TN - 1) / TN, 128, NODE_SMEM_BYTES>>>(
        nf, Wuss, Wuvv, Wusv, Wuvs, WLus, WLuv, out);
}

// round 6
// speedup vs baseline: 5.2004x; 3.3176x over previous
#include <cuda_runtime.h>
#include <math.h>

#define N_NODES 10000
#define N_EDGES 100000

#define INV_SQRT3    0.57735026918962576f
#define NORM_MSG     0.036084391824351614f   // 1/sqrt(768)
#define NORM_MSG_V3  (0.036084391824351614f * 0.57735026918962576f)
#define NORM_UPD_S   0.011811391307201575f   // 1/sqrt(7168)
#define NORM_UPD_V   0.013975424859373686f   // 1/sqrt(5120)
#define NORM_LIN64   0.125f                  // 1/sqrt(64)
#define NORM_LIN32   0.17677669529663687f    // 1/sqrt(32)

#define ZSTRIDE 4096
// per-node factored message tensor product (norms folded in):
// [0,768)     Zss[v<8][w<96]            = sum_u xs_u Wss[u,v,w] * NORM_MSG
// [768,3072)  Zvv[(v*3+m)<24][w<96]     = sum_u xv_{u,m} Wvv[u,v,w] * NORM_MSG/sqrt3
// [3072,3328) Zsv[v<8][w<32]            = sum_u xs_u Wsv[u,v,w] * NORM_MSG
// [3328,4096) Zvs[v<8][(w*3+m)<96]      = sum_u xv_{u,m} Wvs[u,v,w] * NORM_MSG
__device__ float g_z[(size_t)N_NODES * ZSTRIDE];
__device__ float g_agg[N_NODES * 192];   // [96 scalars | 32x3 vectors] per node

__global__ void zero_agg_kernel() {
    int i = blockIdx.x * blockDim.x + threadIdx.x;
    if (i < N_NODES * 192) g_agg[i] = 0.f;
}

// ============================================================================
// Z PRECOMPUTE: 32 nodes/block, 256 threads.
// ============================================================================
__global__ void __launch_bounds__(256) precompute_z(
    const float* __restrict__ nf,
    const float* __restrict__ Wss, const float* __restrict__ Wvv,
    const float* __restrict__ Wsv, const float* __restrict__ Wvs)
{
    __shared__ float s_xs[32 * 64];
    __shared__ float s_xv[32 * 96];
    const int t = threadIdx.x;
    const int n0 = blockIdx.x * 32;

    for (int i = t; i < 32 * 160; i += 256) {
        int n = i / 160, c = i - n * 160;
        int gn = n0 + n;
        float v = (gn < N_NODES) ? nf[(size_t)gn * 160 + c] : 0.f;
        if (c < 64) s_xs[n * 64 + c] = v; else s_xv[n * 96 + (c - 64)] = v;
    }
    __syncthreads();

    const int ng = t >> 6;        // 8-node group
    const int c0 = t & 63;

    // Zss (K=64 over xs)
    for (int c = c0; c < 768; c += 64) {
        float acc[8] = {0,0,0,0,0,0,0,0};
        #pragma unroll 8
        for (int u = 0; u < 64; u++) {
            float b = Wss[u * 768 + c];
            #pragma unroll
            for (int j = 0; j < 8; j++)
                acc[j] = fmaf(s_xs[(ng * 8 + j) * 64 + u], b, acc[j]);
        }
        #pragma unroll
        for (int j = 0; j < 8; j++) {
            int gn = n0 + ng * 8 + j;
            if (gn < N_NODES) g_z[(size_t)gn * ZSTRIDE + c] = acc[j] * NORM_MSG;
        }
    }
    // Zvv (K=32 over xv[:,m])
    for (int c = c0; c < 2304; c += 64) {
        int v = c / 288, rem = c - v * 288;
        int m = rem / 96, w = rem - m * 96;
        float acc[8] = {0,0,0,0,0,0,0,0};
        #pragma unroll 8
        for (int u = 0; u < 32; u++) {
            float b = Wvv[u * 768 + v * 96 + w];
            #pragma unroll
            for (int j = 0; j < 8; j++)
                acc[j] = fmaf(s_xv[(ng * 8 + j) * 96 + u * 3 + m], b, acc[j]);
        }
        #pragma unroll
        for (int j = 0; j < 8; j++) {
            int gn = n0 + ng * 8 + j;
            if (gn < N_NODES) g_z[(size_t)gn * ZSTRIDE + 768 + c] = acc[j] * NORM_MSG_V3;
        }
    }
    // Zsv (K=64 over xs)
    for (int c = c0; c < 256; c += 64) {
        float acc[8] = {0,0,0,0,0,0,0,0};
        #pragma unroll 8
        for (int u = 0; u < 64; u++) {
            float b = Wsv[u * 256 + c];
            #pragma unroll
            for (int j = 0; j < 8; j++)
                acc[j] = fmaf(s_xs[(ng * 8 + j) * 64 + u], b, acc[j]);
        }
        #pragma unroll
        for (int j = 0; j < 8; j++) {
            int gn = n0 + ng * 8 + j;
            if (gn < N_NODES) g_z[(size_t)gn * ZSTRIDE + 3072 + c] = acc[j] * NORM_MSG;
        }
    }
    // Zvs (K=32 over xv[:,m]); layout [v][w*3+m] so edge reads are contiguous
    for (int c = c0; c < 768; c += 64) {
        int v = c / 96, rem = c - v * 96;
        int w = rem / 3, m = rem - w * 3;
        float acc[8] = {0,0,0,0,0,0,0,0};
        #pragma unroll 8
        for (int u = 0; u < 32; u++) {
            float b = Wvs[u * 256 + v * 32 + w];
            #pragma unroll
            for (int j = 0; j < 8; j++)
                acc[j] = fmaf(s_xv[(ng * 8 + j) * 96 + u * 3 + m], b, acc[j]);
        }
        #pragma unroll
        for (int j = 0; j < 8; j++) {
            int gn = n0 + ng * 8 + j;
            if (gn < N_NODES) g_z[(size_t)gn * ZSTRIDE + 3328 + c] = acc[j] * NORM_MSG;
        }
    }
}

// ============================================================================
// EDGE KERNEL: warp-per-edge, 8 edges / 256-thread block.
// TP via Z gather -> gate -> linear -> atomic scatter.
// ============================================================================
#define EB 8
__global__ void __launch_bounds__(256) edge_kernel(
    const float* __restrict__ ea,
    const float* __restrict__ WLs, const float* __restrict__ WLv,
    const int* __restrict__ eidx)
{
    __shared__ float s_WLs[64 * 96];
    __shared__ float s_WLv[32 * 32];
    __shared__ float s_y [EB * 32];
    __shared__ float s_ms[EB * 96];
    __shared__ float s_mv[EB * 96];

    const int t = threadIdx.x;
    for (int i = t; i < 6144; i += 256) s_WLs[i] = WLs[i];
    for (int i = t; i < 1024; i += 256) s_WLv[i] = WLv[i];

    const int es = t >> 5, l = t & 31;
    const int e = blockIdx.x * EB + es;
    s_y[es * 32 + l] = ea[(size_t)e * 32 + l];
    __syncthreads();

    const int row = eidx[e];
    const int col = eidx[N_EDGES + e];
    const float* Z  = g_z + (size_t)col * ZSTRIDE;
    const float* ye = s_y + es * 32;
    float* ms = s_ms + es * 96;
    float* mv = s_mv + es * 96;

    // ms[w] = sum_{q<32} y_q * Z[q*96+w]  (q<8: Zss rows, q>=8: Zvv rows)
    float a0 = 0.f, a1 = 0.f, a2 = 0.f;
    #pragma unroll 8
    for (int q = 0; q < 32; q++) {
        float y = ye[q];
        const float* zr = Z + q * 96;
        a0 = fmaf(y, zr[l],      a0);
        a1 = fmaf(y, zr[l + 32], a1);
        a2 = fmaf(y, zr[l + 64], a2);
    }
    ms[l]      = a0 / (1.f + expf(-a0));   // silu plain
    ms[32 + l] = a1 / (1.f + expf(-a1));
    ms[64 + l] = 1.f / (1.f + expf(-a2));  // sigmoid gate
    __syncwarp();

    // mv[w*3+m] = sum_v ys_v*Zvs[v][c] + yv[v,m]*Zsv[v][w], gated
    const float* Zsv = Z + 3072;
    const float* Zvs = Z + 3328;
    #pragma unroll
    for (int cc = 0; cc < 3; cc++) {
        int c = l + cc * 32;
        int w = c / 3, m = c - w * 3;
        float acc = 0.f;
        #pragma unroll
        for (int v = 0; v < 8; v++) {
            acc = fmaf(ye[v],             Zvs[v * 96 + c], acc);
            acc = fmaf(ye[8 + v * 3 + m], Zsv[v * 32 + w], acc);
        }
        mv[c] = acc * ms[64 + w];
    }
    __syncwarp();

    const size_t base = (size_t)row * 192;
    #pragma unroll
    for (int cc = 0; cc < 3; cc++) {
        int w = l + cc * 32;
        float acc = 0.f;
        #pragma unroll 8
        for (int u = 0; u < 64; u++)
            acc = fmaf(ms[u], s_WLs[u * 96 + w], acc);
        atomicAdd(&g_agg[base + w], acc * NORM_LIN64);
    }
    #pragma unroll
    for (int cc = 0; cc < 3; cc++) {
        int c = l + cc * 32;
        int w = c / 3, m = c - w * 3;
        float acc = 0.f;
        #pragma unroll
        for (int u = 0; u < 32; u++)
            acc = fmaf(mv[u * 3 + m], s_WLv[u * 32 + w], acc);
        atomicAdd(&g_agg[base + 96 + c], acc * NORM_LIN32);
    }
}

// ============================================================================
// NODE KERNEL: 32 nodes/block, 256 threads, double-buffered K-chunked GEMMs.
// ============================================================================
#define NODE_SMEM_BYTES (26624 * 4)

__device__ __forceinline__ void build_a1(const float* s_xs, const float* s_as,
                                         const float* s_xv, const float* s_av,
                                         int k, int ng4, float* r4) {
    if (k < 6144) {
        int u = k / 96, v = k - u * 96;
        #pragma unroll
        for (int j = 0; j < 4; j++) {
            int n = ng4 + j;
            r4[j] = s_xs[n * 64 + u] * s_as[n * 96 + v];
        }
    } else {
        int k2 = k - 6144, u = k2 >> 5, v = k2 & 31;
        #pragma unroll
        for (int j = 0; j < 4; j++) {
            int n = ng4 + j;
            const float* x = s_xv + n * 96 + u * 3;
            const float* a = s_av + n * 96 + v * 3;
            r4[j] = INV_SQRT3 * (x[0]*a[0] + x[1]*a[1] + x[2]*a[2]);
        }
    }
}

__device__ __forceinline__ void build_a2(const float* s_xs, const float* s_as,
                                         const float* s_xv, const float* s_av,
                                         int k, int r0, float* r12) {
    if (k < 2048) {
        int u = k >> 5, v = k & 31;
        #pragma unroll
        for (int j = 0; j < 12; j++) {
            int r = r0 + j, m = r >> 5, n = r & 31;
            r12[j] = s_xs[n * 64 + u] * s_av[n * 96 + v * 3 + m];
        }
    } else {
        int k2 = k - 2048, u = k2 / 96, v = k2 - u * 96;
        #pragma unroll
        for (int j = 0; j < 12; j++) {
            int r = r0 + j, m = r >> 5, n = r & 31;
            r12[j] = s_xv[n * 96 + u * 3 + m] * s_as[n * 96 + v];
        }
    }
}

__global__ void __launch_bounds__(256) node_kernel(
    const float* __restrict__ nf,
    const float* __restrict__ Wss, const float* __restrict__ Wvv,
    const float* __restrict__ Wsv, const float* __restrict__ Wvs,
    const float* __restrict__ WLs, const float* __restrict__ WLv,
    float* __restrict__ out)
{
    extern __shared__ float sm[];
    float* s_xs = sm;            // 2048 [n][u<64]
    float* s_xv = sm + 2048;     // 3072 [n][u*3+m]
    float* s_as = sm + 5120;     // 3072 [n][v<96]
    float* s_av = sm + 8192;     // 3072 [n][v*3+m]
    float* sA   = sm + 11264;    // 2 x 3072
    float* sB   = sm + 17408;    // 2 x 3072
    float* s_us = sm + 23552;    // 3072 [n][w<96]

    const int t  = threadIdx.x;
    const int n0 = blockIdx.x * 32;

    for (int i = t; i < 32 * 160; i += 256) {
        int n = i / 160, c = i - n * 160;
        int gn = n0 + n;
        float v = (gn < N_NODES) ? nf[(size_t)gn * 160 + c] : 0.f;
        if (c < 64) s_xs[n * 64 + c] = v; else s_xv[n * 96 + (c - 64)] = v;
    }
    for (int i = t; i < 32 * 192; i += 256) {
        int n = i / 192, c = i - n * 192;
        int gn = n0 + n;
        float v = (gn < N_NODES) ? g_agg[(size_t)gn * 192 + c] : 0.f;
        if (c < 96) s_as[n * 96 + c] = v; else s_av[n * 96 + (c - 96)] = v;
    }
    __syncthreads();

    const int kkA = t >> 3;          // staging: chunk-k lane
    const int ng4 = (t & 7) * 4;     // stage-1 A staging: 4 nodes
    const int w12 = (t & 7) * 12;    // stage-1 B staging: 12 w
    const int r12 = (t & 7) * 12;    // stage-2 A staging: 12 rows
    const int w4  = (t & 7) * 4;     // stage-2 B staging: 4 w

    // ------------------------- stage 1: us, K=7168 -------------------------
    {
        const int tn4 = (t & 7) * 4;     // compute: 4 nodes (float4 A)
        const int tw3 = (t >> 3) * 3;    // compute: 3 w
        float acc[12];
        #pragma unroll
        for (int i = 0; i < 12; i++) acc[i] = 0.f;

        {   // prologue: chunk 0 (k<32 always in Wss)
            float r4[4];
            build_a1(s_xs, s_as, s_xv, s_av, kkA, ng4, r4);
            #pragma unroll
            for (int j = 0; j < 4; j++) sA[kkA * 32 + ng4 + j] = r4[j];
            const float* src = Wss + (size_t)kkA * 96 + w12;
            *(float4*)&sB[kkA * 96 + w12    ] = *(const float4*)(src);
            *(float4*)&sB[kkA * 96 + w12 + 4] = *(const float4*)(src + 4);
            *(float4*)&sB[kkA * 96 + w12 + 8] = *(const float4*)(src + 8);
        }
        __syncthreads();

        int cur = 0;
        for (int c = 0; c < 224; c++) {
            float r4[4];
            float4 rb0, rb1, rb2;
            const bool pre = (c + 1 < 224);
            if (pre) {
                int k = (c + 1) * 32 + kkA;
                const float* src = (k < 6144) ? Wss + (size_t)k * 96 + w12
                                              : Wvv + (size_t)(k - 6144) * 96 + w12;
                rb0 = *(const float4*)(src);
                rb1 = *(const float4*)(src + 4);
                rb2 = *(const float4*)(src + 8);
                build_a1(s_xs, s_as, s_xv, s_av, k, ng4, r4);
            }
            const float* A = sA + cur * 3072;
            const float* B = sB + cur * 3072;
            #pragma unroll
            for (int kk = 0; kk < 32; kk++) {
                float4 av = *(const float4*)&A[kk * 32 + tn4];
                const float* b = B + kk * 96 + tw3;
                float b0 = b[0], b1 = b[1], b2 = b[2];
                acc[0]  = fmaf(av.x, b0, acc[0]);
                acc[1]  = fmaf(av.x, b1, acc[1]);
                acc[2]  = fmaf(av.x, b2, acc[2]);
                acc[3]  = fmaf(av.y, b0, acc[3]);
                acc[4]  = fmaf(av.y, b1, acc[4]);
                acc[5]  = fmaf(av.y, b2, acc[5]);
                acc[6]  = fmaf(av.z, b0, acc[6]);
                acc[7]  = fmaf(av.z, b1, acc[7]);
                acc[8]  = fmaf(av.z, b2, acc[8]);
                acc[9]  = fmaf(av.w, b0, acc[9]);
                acc[10] = fmaf(av.w, b1, acc[10]);
                acc[11] = fmaf(av.w, b2, acc[11]);
            }
            if (pre) {
                float* An = sA + (cur ^ 1) * 3072;
                float* Bn = sB + (cur ^ 1) * 3072;
                #pragma unroll
                for (int j = 0; j < 4; j++) An[kkA * 32 + ng4 + j] = r4[j];
                *(float4*)&Bn[kkA * 96 + w12    ] = rb0;
                *(float4*)&Bn[kkA * 96 + w12 + 4] = rb1;
                *(float4*)&Bn[kkA * 96 + w12 + 8] = rb2;
            }
            __syncthreads();
            cur ^= 1;
        }
        #pragma unroll
        for (int i = 0; i < 4; i++)
            #pragma unroll
            for (int j = 0; j < 3; j++)
                s_us[(tn4 + i) * 96 + tw3 + j] = acc[i * 3 + j] * NORM_UPD_S;
    }

    // ------------------------- stage 2: uv, K=5120 -------------------------
    {
        const int tr6 = (t >> 4) * 6;    // compute: 6 rows (float2 x3)
        const int tw2 = (t & 15) * 2;    // compute: 2 w (float2)
        float acc2[12];
        #pragma unroll
        for (int i = 0; i < 12; i++) acc2[i] = 0.f;

        {   // prologue: chunk 0 (k<32 always in Wsv)
            float ra[12];
            build_a2(s_xs, s_as, s_xv, s_av, kkA, r12, ra);
            #pragma unroll
            for (int j = 0; j < 12; j++) sA[kkA * 96 + r12 + j] = ra[j];
            *(float4*)&sB[kkA * 32 + w4] = *(const float4*)(Wsv + (size_t)kkA * 32 + w4);
        }
        __syncthreads();

        int cur = 0;
        for (int c = 0; c < 160; c++) {
            float ra[12];
            float4 rb;
            const bool pre = (c + 1 < 160);
            if (pre) {
                int k = (c + 1) * 32 + kkA;
                const float* src = (k < 2048) ? Wsv + (size_t)k * 32 + w4
                                              : Wvs + (size_t)(k - 2048) * 32 + w4;
                rb = *(const float4*)src;
                build_a2(s_xs, s_as, s_xv, s_av, k, r12, ra);
            }
            const float* A = sA + cur * 3072;
            const float* B = sB + cur * 3072;
            #pragma unroll
            for (int kk = 0; kk < 32; kk++) {
                float2 a01 = *(const float2*)&A[kk * 96 + tr6];
                float2 a23 = *(const float2*)&A[kk * 96 + tr6 + 2];
                float2 a45 = *(const float2*)&A[kk * 96 + tr6 + 4];
                float2 b   = *(const float2*)&B[kk * 32 + tw2];
                acc2[0]  = fmaf(a01.x, b.x, acc2[0]);
                acc2[1]  = fmaf(a01.x, b.y, acc2[1]);
                acc2[2]  = fmaf(a01.y, b.x, acc2[2]);
                acc2[3]  = fmaf(a01.y, b.y, acc2[3]);
                acc2[4]  = fmaf(a23.x, b.x, acc2[4]);
                acc2[5]  = fmaf(a23.x, b.y, acc2[5]);
                acc2[6]  = fmaf(a23.y, b.x, acc2[6]);
                acc2[7]  = fmaf(a23.y, b.y, acc2[7]);
                acc2[8]  = fmaf(a45.x, b.x, acc2[8]);
                acc2[9]  = fmaf(a45.x, b.y, acc2[9]);
                acc2[10] = fmaf(a45.y, b.x, acc2[10]);
                acc2[11] = fmaf(a45.y, b.y, acc2[11]);
            }
            if (pre) {
                float* An = sA + (cur ^ 1) * 3072;
                float* Bn = sB + (cur ^ 1) * 3072;
                #pragma unroll
                for (int j = 0; j < 12; j++) An[kkA * 96 + r12 + j] = ra[j];
                *(float4*)&Bn[kkA * 32 + w4] = rb;
            }
            __syncthreads();
            cur ^= 1;
        }
        // uv -> sA buffer 0 (region distinct from last compute buffer; synced below)
        float* s_uv = sA;
        #pragma unroll
        for (int i = 0; i < 6; i++)
            #pragma unroll
            for (int j = 0; j < 2; j++)
                s_uv[(tr6 + i) * 32 + tw2 + j] = acc2[i * 2 + j] * NORM_UPD_V;
    }
    __syncthreads();

    // ------------------------- epilogue -------------------------
    float* s_uv   = sA;           // 3072: [m*32+n][u<32]
    float* s_WL   = sB;           // WLs 4096
    float* s_WLv2 = sB + 4096;    // WLv 1024
    float* s_g    = s_as;         // gates 1024 (s_as dead)

    for (int i = t; i < 4096; i += 256) s_WL[i] = WLs[i];
    for (int i = t; i < 1024; i += 256) s_WLv2[i] = WLv[i];
    for (int i = t; i < 2048; i += 256) {
        int n = i >> 6, u = i & 63;
        float x = s_us[n * 96 + u];
        s_us[n * 96 + u] = x / (1.f + expf(-x));
    }
    for (int i = t; i < 1024; i += 256) {
        int n = i >> 5, w = i & 31;
        s_g[i] = 1.f / (1.f + expf(-s_us[n * 96 + 64 + w]));
    }
    __syncthreads();
    for (int i = t; i < 3072; i += 256) {
        int r = i >> 5, u = i & 31;
        int n = r & 31;
        s_uv[i] *= s_g[n * 32 + u];
    }
    __syncthreads();

    for (int i = t; i < 2048; i += 256) {
        int n = i >> 6, w = i & 63;
        int gn = n0 + n;
        if (gn < N_NODES) {
            float s = 0.f;
            #pragma unroll 8
            for (int u = 0; u < 64; u++)
                s = fmaf(s_us[n * 96 + u], s_WL[u * 64 + w], s);
            out[(size_t)gn * 160 + w] = s_xs[n * 64 + w] + s * NORM_LIN64;
        }
    }
    for (int i = t; i < 3072; i += 256) {
        int n = i / 96, c = i - n * 96;
        int w = c / 3, m = c - w * 3;
        int gn = n0 + n;
        if (gn < N_NODES) {
            float s = 0.f;
            #pragma unroll
            for (int u = 0; u < 32; u++)
                s = fmaf(s_uv[(m * 32 + n) * 32 + u], s_WLv2[u * 32 + w], s);
            out[(size_t)gn * 160 + 64 + c] = s_xv[n * 96 + c] + s * NORM_LIN32;
        }
    }
}

extern "C" void kernel_launch(void* const* d_in, const int* in_sizes, int n_in,
                              void* d_out, int out_size) {
    const float* nf   = (const float*)d_in[0];
    const float* ea   = (const float*)d_in[1];
    const float* Wmss = (const float*)d_in[2];
    const float* Wmvv = (const float*)d_in[3];
    const float* Wmsv = (const float*)d_in[4];
    const float* Wmvs = (const float*)d_in[5];
    const float* WLms = (const float*)d_in[6];
    const float* WLmv = (const float*)d_in[7];
    const float* Wuss = (const float*)d_in[8];
    const float* Wuvv = (const float*)d_in[9];
    const float* Wusv = (const float*)d_in[10];
    const float* Wuvs = (const float*)d_in[11];
    const float* WLus = (const float*)d_in[12];
    const float* WLuv = (const float*)d_in[13];
    const int*   eidx = (const int*)d_in[14];
    float* out = (float*)d_out;

    cudaFuncSetAttribute(node_kernel, cudaFuncAttributeMaxDynamicSharedMemorySize,
                         NODE_SMEM_BYTES);

    zero_agg_kernel<<<(N_NODES * 192 + 255) / 256, 256>>>();
    precompute_z<<<(N_NODES + 31) / 32, 256>>>(nf, Wmss, Wmvv, Wmsv, Wmvs);
    edge_kernel<<<N_EDGES / EB, 256>>>(ea, WLms, WLmv, eidx);
    node_kernel<<<(N_NODES + 31) / 32, 256, NODE_SMEM_BYTES>>>(
        nf, Wuss, Wuvv, Wusv, Wuvs, WLus, WLuv, out);
}

// round 7
// speedup vs baseline: 6.9886x; 1.3439x over previous
#include <cuda_runtime.h>
#include <math.h>

#define N_NODES 10000
#define N_EDGES 100000

#define INV_SQRT3    0.57735026918962576f
#define NORM_MSG     0.036084391824351614f   // 1/sqrt(768)
#define NORM_MSG_V3  (0.036084391824351614f * 0.57735026918962576f)
#define NORM_UPD_S   0.011811391307201575f   // 1/sqrt(7168)
#define NORM_UPD_V   0.013975424859373686f   // 1/sqrt(5120)
#define NORM_LIN64   0.125f                  // 1/sqrt(64)
#define NORM_LIN32   0.17677669529663687f    // 1/sqrt(32)

#define ZSTRIDE 4096
// per-node factored message tensor product (norms folded in):
// [0,768)     Zss[v<8][w<96], [768,3072) Zvv[(v*3+m)<24][w<96],
// [3072,3328) Zsv[v<8][w<32], [3328,4096) Zvs[v<8][(w*3+m)<96]
__device__ float g_z[(size_t)N_NODES * ZSTRIDE];
__device__ float g_agg[N_NODES * 192];   // [96 scalars | 32x3 vectors] per node

__global__ void zero_agg_kernel() {
    int i = blockIdx.x * blockDim.x + threadIdx.x;
    if (i < N_NODES * 192) g_agg[i] = 0.f;
}

// ============================================================================
// Z PRECOMPUTE: 32 nodes/block, 256 threads.  (unchanged)
// ============================================================================
__global__ void __launch_bounds__(256) precompute_z(
    const float* __restrict__ nf,
    const float* __restrict__ Wss, const float* __restrict__ Wvv,
    const float* __restrict__ Wsv, const float* __restrict__ Wvs)
{
    __shared__ float s_xs[32 * 64];
    __shared__ float s_xv[32 * 96];
    const int t = threadIdx.x;
    const int n0 = blockIdx.x * 32;

    for (int i = t; i < 32 * 160; i += 256) {
        int n = i / 160, c = i - n * 160;
        int gn = n0 + n;
        float v = (gn < N_NODES) ? nf[(size_t)gn * 160 + c] : 0.f;
        if (c < 64) s_xs[n * 64 + c] = v; else s_xv[n * 96 + (c - 64)] = v;
    }
    __syncthreads();

    const int ng = t >> 6;
    const int c0 = t & 63;

    for (int c = c0; c < 768; c += 64) {
        float acc[8] = {0,0,0,0,0,0,0,0};
        #pragma unroll 8
        for (int u = 0; u < 64; u++) {
            float b = Wss[u * 768 + c];
            #pragma unroll
            for (int j = 0; j < 8; j++)
                acc[j] = fmaf(s_xs[(ng * 8 + j) * 64 + u], b, acc[j]);
        }
        #pragma unroll
        for (int j = 0; j < 8; j++) {
            int gn = n0 + ng * 8 + j;
            if (gn < N_NODES) g_z[(size_t)gn * ZSTRIDE + c] = acc[j] * NORM_MSG;
        }
    }
    for (int c = c0; c < 2304; c += 64) {
        int v = c / 288, rem = c - v * 288;
        int m = rem / 96, w = rem - m * 96;
        float acc[8] = {0,0,0,0,0,0,0,0};
        #pragma unroll 8
        for (int u = 0; u < 32; u++) {
            float b = Wvv[u * 768 + v * 96 + w];
            #pragma unroll
            for (int j = 0; j < 8; j++)
                acc[j] = fmaf(s_xv[(ng * 8 + j) * 96 + u * 3 + m], b, acc[j]);
        }
        #pragma unroll
        for (int j = 0; j < 8; j++) {
            int gn = n0 + ng * 8 + j;
            if (gn < N_NODES) g_z[(size_t)gn * ZSTRIDE + 768 + c] = acc[j] * NORM_MSG_V3;
        }
    }
    for (int c = c0; c < 256; c += 64) {
        float acc[8] = {0,0,0,0,0,0,0,0};
        #pragma unroll 8
        for (int u = 0; u < 64; u++) {
            float b = Wsv[u * 256 + c];
            #pragma unroll
            for (int j = 0; j < 8; j++)
                acc[j] = fmaf(s_xs[(ng * 8 + j) * 64 + u], b, acc[j]);
        }
        #pragma unroll
        for (int j = 0; j < 8; j++) {
            int gn = n0 + ng * 8 + j;
            if (gn < N_NODES) g_z[(size_t)gn * ZSTRIDE + 3072 + c] = acc[j] * NORM_MSG;
        }
    }
    for (int c = c0; c < 768; c += 64) {
        int v = c / 96, rem = c - v * 96;
        int w = rem / 3, m = rem - w * 3;
        float acc[8] = {0,0,0,0,0,0,0,0};
        #pragma unroll 8
        for (int u = 0; u < 32; u++) {
            float b = Wvs[u * 256 + v * 32 + w];
            #pragma unroll
            for (int j = 0; j < 8; j++)
                acc[j] = fmaf(s_xv[(ng * 8 + j) * 96 + u * 3 + m], b, acc[j]);
        }
        #pragma unroll
        for (int j = 0; j < 8; j++) {
            int gn = n0 + ng * 8 + j;
            if (gn < N_NODES) g_z[(size_t)gn * ZSTRIDE + 3328 + c] = acc[j] * NORM_MSG;
        }
    }
}

// ============================================================================
// EDGE KERNEL: warp-per-edge, 8 edges / 256-thread block.  (unchanged)
// ============================================================================
#define EB 8
__global__ void __launch_bounds__(256) edge_kernel(
    const float* __restrict__ ea,
    const float* __restrict__ WLs, const float* __restrict__ WLv,
    const int* __restrict__ eidx)
{
    __shared__ float s_WLs[64 * 96];
    __shared__ float s_WLv[32 * 32];
    __shared__ float s_y [EB * 32];
    __shared__ float s_ms[EB * 96];
    __shared__ float s_mv[EB * 96];

    const int t = threadIdx.x;
    for (int i = t; i < 6144; i += 256) s_WLs[i] = WLs[i];
    for (int i = t; i < 1024; i += 256) s_WLv[i] = WLv[i];

    const int es = t >> 5, l = t & 31;
    const int e = blockIdx.x * EB + es;
    s_y[es * 32 + l] = ea[(size_t)e * 32 + l];
    __syncthreads();

    const int row = eidx[e];
    const int col = eidx[N_EDGES + e];
    const float* Z  = g_z + (size_t)col * ZSTRIDE;
    const float* ye = s_y + es * 32;
    float* ms = s_ms + es * 96;
    float* mv = s_mv + es * 96;

    float a0 = 0.f, a1 = 0.f, a2 = 0.f;
    #pragma unroll 8
    for (int q = 0; q < 32; q++) {
        float y = ye[q];
        const float* zr = Z + q * 96;
        a0 = fmaf(y, zr[l],      a0);
        a1 = fmaf(y, zr[l + 32], a1);
        a2 = fmaf(y, zr[l + 64], a2);
    }
    ms[l]      = a0 / (1.f + expf(-a0));
    ms[32 + l] = a1 / (1.f + expf(-a1));
    ms[64 + l] = 1.f / (1.f + expf(-a2));
    __syncwarp();

    const float* Zsv = Z + 3072;
    const float* Zvs = Z + 3328;
    #pragma unroll
    for (int cc = 0; cc < 3; cc++) {
        int c = l + cc * 32;
        int w = c / 3, m = c - w * 3;
        float acc = 0.f;
        #pragma unroll
        for (int v = 0; v < 8; v++) {
            acc = fmaf(ye[v],             Zvs[v * 96 + c], acc);
            acc = fmaf(ye[8 + v * 3 + m], Zsv[v * 32 + w], acc);
        }
        mv[c] = acc * ms[64 + w];
    }
    __syncwarp();

    const size_t base = (size_t)row * 192;
    #pragma unroll
    for (int cc = 0; cc < 3; cc++) {
        int w = l + cc * 32;
        float acc = 0.f;
        #pragma unroll 8
        for (int u = 0; u < 64; u++)
            acc = fmaf(ms[u], s_WLs[u * 96 + w], acc);
        atomicAdd(&g_agg[base + w], acc * NORM_LIN64);
    }
    #pragma unroll
    for (int cc = 0; cc < 3; cc++) {
        int c = l + cc * 32;
        int w = c / 3, m = c - w * 3;
        float acc = 0.f;
        #pragma unroll
        for (int u = 0; u < 32; u++)
            acc = fmaf(mv[u * 3 + m], s_WLv[u * 32 + w], acc);
        atomicAdd(&g_agg[base + 96 + c], acc * NORM_LIN32);
    }
}

// ============================================================================
// NODE KERNEL v2: 32 nodes/block, 256 threads, Kc=16, transposed operands,
// unified double-buffered chunk region -> 72KB smem -> 3 blocks/SM.
// smem layout (floats):
//   0      xsT  [64u][32n]           2048
//   2048   xvT  [3m][32u][32n]       3072
//   5120   asT  [96v][32n]           3072   (epilogue: WLs 4096 + WLv 1024 here)
//   8192   avT  [3m][32v][32n]       3072
//   11264  sCh  2 x 2048             4096   (stage1: A 512 | B 1536; stage2: A 1536 | B 512)
//   15360  s_us [32n][96w]           3072
// ============================================================================
#define NODE_SMEM_BYTES (18432 * 4)

__device__ __forceinline__ float2 build1(const float* xsT, const float* asT,
                                         const float* xvT, const float* avT,
                                         int k, int n2) {
    float2 r;
    if (k < 6144) {
        int u = k / 96, v = k - u * 96;
        float2 x = *(const float2*)&xsT[u * 32 + n2];
        float2 a = *(const float2*)&asT[v * 32 + n2];
        r.x = x.x * a.x; r.y = x.y * a.y;
    } else {
        int k2 = k - 6144, u = k2 >> 5, v = k2 & 31;
        float sx = 0.f, sy = 0.f;
        #pragma unroll
        for (int m = 0; m < 3; m++) {
            float2 x = *(const float2*)&xvT[m * 1024 + u * 32 + n2];
            float2 a = *(const float2*)&avT[m * 1024 + v * 32 + n2];
            sx = fmaf(x.x, a.x, sx); sy = fmaf(x.y, a.y, sy);
        }
        r.x = INV_SQRT3 * sx; r.y = INV_SQRT3 * sy;
    }
    return r;
}

__device__ __forceinline__ void build2(const float* xsT, const float* asT,
                                       const float* xvT, const float* avT,
                                       int k, int n2, float2* o3) {
    if (k < 2048) {
        int u = k >> 5, v = k & 31;
        float2 x = *(const float2*)&xsT[u * 32 + n2];
        #pragma unroll
        for (int m = 0; m < 3; m++) {
            float2 a = *(const float2*)&avT[m * 1024 + v * 32 + n2];
            o3[m].x = x.x * a.x; o3[m].y = x.y * a.y;
        }
    } else {
        int k2 = k - 2048, u = k2 / 96, v = k2 - u * 96;
        float2 a = *(const float2*)&asT[v * 32 + n2];
        #pragma unroll
        for (int m = 0; m < 3; m++) {
            float2 x = *(const float2*)&xvT[m * 1024 + u * 32 + n2];
            o3[m].x = x.x * a.x; o3[m].y = x.y * a.y;
        }
    }
}

__global__ void __launch_bounds__(256, 3) node_kernel(
    const float* __restrict__ nf,
    const float* __restrict__ Wss, const float* __restrict__ Wvv,
    const float* __restrict__ Wsv, const float* __restrict__ Wvs,
    const float* __restrict__ WLs, const float* __restrict__ WLv,
    float* __restrict__ out)
{
    extern __shared__ float sm[];
    float* s_xsT = sm;
    float* s_xvT = sm + 2048;
    float* s_asT = sm + 5120;
    float* s_avT = sm + 8192;
    float* sCh   = sm + 11264;
    float* s_us  = sm + 15360;

    const int t  = threadIdx.x;
    const int n0 = blockIdx.x * 32;

    // load + transpose inputs
    for (int i = t; i < 32 * 160; i += 256) {
        int n = i / 160, c = i - n * 160;
        int gn = n0 + n;
        float v = (gn < N_NODES) ? nf[(size_t)gn * 160 + c] : 0.f;
        if (c < 64) s_xsT[c * 32 + n] = v;
        else { int c2 = c - 64, u = c2 / 3, m = c2 - u * 3;
               s_xvT[m * 1024 + u * 32 + n] = v; }
    }
    for (int i = t; i < 32 * 192; i += 256) {
        int n = i / 192, c = i - n * 192;
        int gn = n0 + n;
        float v = (gn < N_NODES) ? g_agg[(size_t)gn * 192 + c] : 0.f;
        if (c < 96) s_asT[c * 32 + n] = v;
        else { int c2 = c - 96, w = c2 / 3, m = c2 - w * 3;
               s_avT[m * 1024 + w * 32 + n] = v; }
    }
    __syncthreads();

    // thread maps
    const int kb  = t >> 4;            // build kk (16)
    const int n2b = (t & 15) * 2;      // build node pair
    const int bL  = t * 6;             // stage1 B: 6 floats
    const int kB1 = bL / 96, wB1 = bL - kB1 * 96;
    const int w2B = (t & 15) * 2;      // stage2 B: 2 floats, row kb

    // ------------------------- stage 1: us, K=7168, 448 chunks -------------
    {
        const int n2c = (t & 15) * 2;
        const int w6  = (t >> 4) * 6;
        float acc[12];
        #pragma unroll
        for (int i = 0; i < 12; i++) acc[i] = 0.f;

        {   // prologue chunk 0 (all k<16: ss region)
            float2 a0 = build1(s_xsT, s_asT, s_xvT, s_avT, kb, n2b);
            *(float2*)&sCh[kb * 32 + n2b] = a0;
            const float* src = Wss + (size_t)kB1 * 96 + wB1;
            *(float2*)&sCh[512 + kB1 * 96 + wB1    ] = *(const float2*)(src);
            *(float2*)&sCh[512 + kB1 * 96 + wB1 + 2] = *(const float2*)(src + 2);
            *(float2*)&sCh[512 + kB1 * 96 + wB1 + 4] = *(const float2*)(src + 4);
        }
        __syncthreads();

        int cur = 0;
        for (int c = 0; c < 448; c++) {
            float2 an, bn0, bn1, bn2;
            const bool pre = (c + 1 < 448);
            if (pre) {
                int kbase = (c + 1) * 16;
                int kw = kbase + kB1;
                const float* src = (kw < 6144) ? Wss + (size_t)kw * 96 + wB1
                                               : Wvv + (size_t)(kw - 6144) * 96 + wB1;
                bn0 = *(const float2*)(src);
                bn1 = *(const float2*)(src + 2);
                bn2 = *(const float2*)(src + 4);
                an = build1(s_xsT, s_asT, s_xvT, s_avT, kbase + kb, n2b);
            }
            const float* A = sCh + cur * 2048;
            const float* B = A + 512;
            #pragma unroll
            for (int kk = 0; kk < 16; kk++) {
                float2 a  = *(const float2*)&A[kk * 32 + n2c];
                float2 b0 = *(const float2*)&B[kk * 96 + w6];
                float2 b1 = *(const float2*)&B[kk * 96 + w6 + 2];
                float2 b2 = *(const float2*)&B[kk * 96 + w6 + 4];
                acc[0]  = fmaf(a.x, b0.x, acc[0]);
                acc[1]  = fmaf(a.x, b0.y, acc[1]);
                acc[2]  = fmaf(a.x, b1.x, acc[2]);
                acc[3]  = fmaf(a.x, b1.y, acc[3]);
                acc[4]  = fmaf(a.x, b2.x, acc[4]);
                acc[5]  = fmaf(a.x, b2.y, acc[5]);
                acc[6]  = fmaf(a.y, b0.x, acc[6]);
                acc[7]  = fmaf(a.y, b0.y, acc[7]);
                acc[8]  = fmaf(a.y, b1.x, acc[8]);
                acc[9]  = fmaf(a.y, b1.y, acc[9]);
                acc[10] = fmaf(a.y, b2.x, acc[10]);
                acc[11] = fmaf(a.y, b2.y, acc[11]);
            }
            if (pre) {
                float* An = sCh + (cur ^ 1) * 2048;
                float* Bn = An + 512;
                *(float2*)&An[kb * 32 + n2b] = an;
                *(float2*)&Bn[kB1 * 96 + wB1    ] = bn0;
                *(float2*)&Bn[kB1 * 96 + wB1 + 2] = bn1;
                *(float2*)&Bn[kB1 * 96 + wB1 + 4] = bn2;
            }
            __syncthreads();
            cur ^= 1;
        }
        #pragma unroll
        for (int j = 0; j < 6; j++) {
            s_us[(n2c + 0) * 96 + w6 + j] = acc[j]     * NORM_UPD_S;
            s_us[(n2c + 1) * 96 + w6 + j] = acc[6 + j] * NORM_UPD_S;
        }
    }

    // ------------------------- stage 2: uv, K=5120, 320 chunks -------------
    {
        const int r6  = (t & 15) * 6;
        const int w2c = (t >> 4) * 2;
        float acc2[12];
        #pragma unroll
        for (int i = 0; i < 12; i++) acc2[i] = 0.f;

        {   // prologue chunk 0 (k<16: sv region)
            float2 o3[3];
            build2(s_xsT, s_asT, s_xvT, s_avT, kb, n2b, o3);
            #pragma unroll
            for (int m = 0; m < 3; m++)
                *(float2*)&sCh[kb * 96 + m * 32 + n2b] = o3[m];
            *(float2*)&sCh[1536 + kb * 32 + w2B] =
                *(const float2*)(Wsv + (size_t)kb * 32 + w2B);
        }
        __syncthreads();

        int cur = 0;
        for (int c = 0; c < 320; c++) {
            float2 o3n[3], bn;
            const bool pre = (c + 1 < 320);
            if (pre) {
                int kbase = (c + 1) * 16;
                int kw = kbase + kb;
                const float* src = (kw < 2048) ? Wsv + (size_t)kw * 32 + w2B
                                               : Wvs + (size_t)(kw - 2048) * 32 + w2B;
                bn = *(const float2*)src;
                build2(s_xsT, s_asT, s_xvT, s_avT, kbase + kb, n2b, o3n);
            }
            const float* A = sCh + cur * 2048;
            const float* B = A + 1536;
            #pragma unroll
            for (int kk = 0; kk < 16; kk++) {
                float2 a0 = *(const float2*)&A[kk * 96 + r6];
                float2 a1 = *(const float2*)&A[kk * 96 + r6 + 2];
                float2 a2 = *(const float2*)&A[kk * 96 + r6 + 4];
                float2 b  = *(const float2*)&B[kk * 32 + w2c];
                acc2[0]  = fmaf(a0.x, b.x, acc2[0]);
                acc2[1]  = fmaf(a0.x, b.y, acc2[1]);
                acc2[2]  = fmaf(a0.y, b.x, acc2[2]);
                acc2[3]  = fmaf(a0.y, b.y, acc2[3]);
                acc2[4]  = fmaf(a1.x, b.x, acc2[4]);
                acc2[5]  = fmaf(a1.x, b.y, acc2[5]);
                acc2[6]  = fmaf(a1.y, b.x, acc2[6]);
                acc2[7]  = fmaf(a1.y, b.y, acc2[7]);
                acc2[8]  = fmaf(a2.x, b.x, acc2[8]);
                acc2[9]  = fmaf(a2.x, b.y, acc2[9]);
                acc2[10] = fmaf(a2.y, b.x, acc2[10]);
                acc2[11] = fmaf(a2.y, b.y, acc2[11]);
            }
            if (pre) {
                float* An = sCh + (cur ^ 1) * 2048;
                float* Bn = An + 1536;
                #pragma unroll
                for (int m = 0; m < 3; m++)
                    *(float2*)&An[kb * 96 + m * 32 + n2b] = o3n[m];
                *(float2*)&Bn[kb * 32 + w2B] = bn;
            }
            __syncthreads();
            cur ^= 1;
        }
        // store uv TRANSPOSED: s_uvT[w<32][r<96] into sCh (both buffers dead)
        float* s_uvT = sCh;
        #pragma unroll
        for (int i = 0; i < 6; i++) {
            s_uvT[(w2c + 0) * 96 + r6 + i] = acc2[i * 2]     * NORM_UPD_V;
            s_uvT[(w2c + 1) * 96 + r6 + i] = acc2[i * 2 + 1] * NORM_UPD_V;
        }
    }

    // ------------------------- epilogue -------------------------
    float* s_uvT = sCh;            // [w<32][r=m*32+n]
    float* s_gT  = sCh + 3072;     // [w<32][n<32]
    float* s_WL  = s_asT;          // WLs 4096 (asT+avT dead)
    float* s_WLv = s_asT + 4096;   // WLv 1024

    for (int i = t; i < 4096; i += 256) s_WL[i] = WLs[i];
    for (int i = t; i < 1024; i += 256) s_WLv[i] = WLv[i];
    for (int i = t; i < 2048; i += 256) {
        int n = i >> 6, u = i & 63;
        float x = s_us[n * 96 + u];
        s_us[n * 96 + u] = x / (1.f + expf(-x));
    }
    for (int i = t; i < 1024; i += 256) {
        int w = i >> 5, n = i & 31;
        s_gT[i] = 1.f / (1.f + expf(-s_us[n * 96 + 64 + w]));
    }
    __syncthreads();
    for (int i = t; i < 3072; i += 256) {
        int w = i / 96, r = i - w * 96;
        s_uvT[i] *= s_gT[w * 32 + (r & 31)];
    }
    __syncthreads();

    // scalar out: coalesced, residual from global
    for (int i = t; i < 2048; i += 256) {
        int n = i >> 6, w = i & 63;
        int gn = n0 + n;
        if (gn < N_NODES) {
            float s = 0.f;
            #pragma unroll 8
            for (int u = 0; u < 64; u++)
                s = fmaf(s_us[n * 96 + u], s_WL[u * 64 + w], s);
            out[(size_t)gn * 160 + w] = nf[(size_t)gn * 160 + w] + s * NORM_LIN64;
        }
    }
    // vector out
    for (int i = t; i < 3072; i += 256) {
        int n = i / 96, c = i - n * 96;
        int w = c / 3, m = c - w * 3;
        int gn = n0 + n;
        if (gn < N_NODES) {
            float s = 0.f;
            #pragma unroll
            for (int u = 0; u < 32; u++)
                s = fmaf(s_uvT[u * 96 + m * 32 + n], s_WLv[u * 32 + w], s);
            out[(size_t)gn * 160 + 64 + c] = nf[(size_t)gn * 160 + 64 + c] + s * NORM_LIN32;
        }
    }
}

extern "C" void kernel_launch(void* const* d_in, const int* in_sizes, int n_in,
                              void* d_out, int out_size) {
    const float* nf   = (const float*)d_in[0];
    const float* ea   = (const float*)d_in[1];
    const float* Wmss = (const float*)d_in[2];
    const float* Wmvv = (const float*)d_in[3];
    const float* Wmsv = (const float*)d_in[4];
    const float* Wmvs = (const float*)d_in[5];
    const float* WLms = (const float*)d_in[6];
    const float* WLmv = (const float*)d_in[7];
    const float* Wuss = (const float*)d_in[8];
    const float* Wuvv = (const float*)d_in[9];
    const float* Wusv = (const float*)d_in[10];
    const float* Wuvs = (const float*)d_in[11];
    const float* WLus = (const float*)d_in[12];
    const float* WLuv = (const float*)d_in[13];
    const int*   eidx = (const int*)d_in[14];
    float* out = (float*)d_out;

    cudaFuncSetAttribute(node_kernel, cudaFuncAttributeMaxDynamicSharedMemorySize,
                         NODE_SMEM_BYTES);

    zero_agg_kernel<<<(N_NODES * 192 + 255) / 256, 256>>>();
    precompute_z<<<(N_NODES + 31) / 32, 256>>>(nf, Wmss, Wmvv, Wmsv, Wmvs);
    edge_kernel<<<N_EDGES / EB, 256>>>(ea, WLms, WLmv, eidx);
    node_kernel<<<(N_NODES + 31) / 32, 256, NODE_SMEM_BYTES>>>(
        nf, Wuss, Wuvv, Wusv, Wuvs, WLus, WLuv, out);
}

// round 8
// speedup vs baseline: 7.9372x; 1.1357x over previous
#include <cuda_runtime.h>
#include <math.h>

#define N_NODES 10000
#define N_EDGES 100000

#define INV_SQRT3    0.57735026918962576f
#define NORM_MSG     0.036084391824351614f   // 1/sqrt(768)
#define NORM_MSG_V3  (0.036084391824351614f * 0.57735026918962576f)
#define NORM_UPD_S   0.011811391307201575f   // 1/sqrt(7168)
#define NORM_UPD_V   0.013975424859373686f   // 1/sqrt(5120)
#define NORM_LIN64   0.125f                  // 1/sqrt(64)
#define NORM_LIN32   0.17677669529663687f    // 1/sqrt(32)

#define ZSTRIDE 4096
// per-node factored message tensor product (norms folded in):
// [0,768)     Zss[v<8][w<96], [768,3072) Zvv[(v*3+m)<24][w<96],
// [3072,3328) Zsv[v<8][w<32], [3328,4096) Zvs[v<8][(w*3+m)<96]
__device__ float g_z[(size_t)N_NODES * ZSTRIDE];
__device__ float g_agg[N_NODES * 192];   // [96 scalars | 32x3 vectors] per node

__global__ void zero_agg_kernel() {
    int i = blockIdx.x * blockDim.x + threadIdx.x;
    if (i < N_NODES * 192) g_agg[i] = 0.f;
}

// ============================================================================
// Z PRECOMPUTE: 32 nodes/block, 256 threads.  (unchanged)
// ============================================================================
__global__ void __launch_bounds__(256) precompute_z(
    const float* __restrict__ nf,
    const float* __restrict__ Wss, const float* __restrict__ Wvv,
    const float* __restrict__ Wsv, const float* __restrict__ Wvs)
{
    __shared__ float s_xs[32 * 64];
    __shared__ float s_xv[32 * 96];
    const int t = threadIdx.x;
    const int n0 = blockIdx.x * 32;

    for (int i = t; i < 32 * 160; i += 256) {
        int n = i / 160, c = i - n * 160;
        int gn = n0 + n;
        float v = (gn < N_NODES) ? nf[(size_t)gn * 160 + c] : 0.f;
        if (c < 64) s_xs[n * 64 + c] = v; else s_xv[n * 96 + (c - 64)] = v;
    }
    __syncthreads();

    const int ng = t >> 6;
    const int c0 = t & 63;

    for (int c = c0; c < 768; c += 64) {
        float acc[8] = {0,0,0,0,0,0,0,0};
        #pragma unroll 8
        for (int u = 0; u < 64; u++) {
            float b = Wss[u * 768 + c];
            #pragma unroll
            for (int j = 0; j < 8; j++)
                acc[j] = fmaf(s_xs[(ng * 8 + j) * 64 + u], b, acc[j]);
        }
        #pragma unroll
        for (int j = 0; j < 8; j++) {
            int gn = n0 + ng * 8 + j;
            if (gn < N_NODES) g_z[(size_t)gn * ZSTRIDE + c] = acc[j] * NORM_MSG;
        }
    }
    for (int c = c0; c < 2304; c += 64) {
        int v = c / 288, rem = c - v * 288;
        int m = rem / 96, w = rem - m * 96;
        float acc[8] = {0,0,0,0,0,0,0,0};
        #pragma unroll 8
        for (int u = 0; u < 32; u++) {
            float b = Wvv[u * 768 + v * 96 + w];
            #pragma unroll
            for (int j = 0; j < 8; j++)
                acc[j] = fmaf(s_xv[(ng * 8 + j) * 96 + u * 3 + m], b, acc[j]);
        }
        #pragma unroll
        for (int j = 0; j < 8; j++) {
            int gn = n0 + ng * 8 + j;
            if (gn < N_NODES) g_z[(size_t)gn * ZSTRIDE + 768 + c] = acc[j] * NORM_MSG_V3;
        }
    }
    for (int c = c0; c < 256; c += 64) {
        float acc[8] = {0,0,0,0,0,0,0,0};
        #pragma unroll 8
        for (int u = 0; u < 64; u++) {
            float b = Wsv[u * 256 + c];
            #pragma unroll
            for (int j = 0; j < 8; j++)
                acc[j] = fmaf(s_xs[(ng * 8 + j) * 64 + u], b, acc[j]);
        }
        #pragma unroll
        for (int j = 0; j < 8; j++) {
            int gn = n0 + ng * 8 + j;
            if (gn < N_NODES) g_z[(size_t)gn * ZSTRIDE + 3072 + c] = acc[j] * NORM_MSG;
        }
    }
    for (int c = c0; c < 768; c += 64) {
        int v = c / 96, rem = c - v * 96;
        int w = rem / 3, m = rem - w * 3;
        float acc[8] = {0,0,0,0,0,0,0,0};
        #pragma unroll 8
        for (int u = 0; u < 32; u++) {
            float b = Wvs[u * 256 + v * 32 + w];
            #pragma unroll
            for (int j = 0; j < 8; j++)
                acc[j] = fmaf(s_xv[(ng * 8 + j) * 96 + u * 3 + m], b, acc[j]);
        }
        #pragma unroll
        for (int j = 0; j < 8; j++) {
            int gn = n0 + ng * 8 + j;
            if (gn < N_NODES) g_z[(size_t)gn * ZSTRIDE + 3328 + c] = acc[j] * NORM_MSG;
        }
    }
}

// ============================================================================
// EDGE KERNEL: warp-per-edge, 8 edges / 256-thread block.  (unchanged)
// ============================================================================
#define EB 8
__global__ void __launch_bounds__(256) edge_kernel(
    const float* __restrict__ ea,
    const float* __restrict__ WLs, const float* __restrict__ WLv,
    const int* __restrict__ eidx)
{
    __shared__ float s_WLs[64 * 96];
    __shared__ float s_WLv[32 * 32];
    __shared__ float s_y [EB * 32];
    __shared__ float s_ms[EB * 96];
    __shared__ float s_mv[EB * 96];

    const int t = threadIdx.x;
    for (int i = t; i < 6144; i += 256) s_WLs[i] = WLs[i];
    for (int i = t; i < 1024; i += 256) s_WLv[i] = WLv[i];

    const int es = t >> 5, l = t & 31;
    const int e = blockIdx.x * EB + es;
    s_y[es * 32 + l] = ea[(size_t)e * 32 + l];
    __syncthreads();

    const int row = eidx[e];
    const int col = eidx[N_EDGES + e];
    const float* Z  = g_z + (size_t)col * ZSTRIDE;
    const float* ye = s_y + es * 32;
    float* ms = s_ms + es * 96;
    float* mv = s_mv + es * 96;

    float a0 = 0.f, a1 = 0.f, a2 = 0.f;
    #pragma unroll 8
    for (int q = 0; q < 32; q++) {
        float y = ye[q];
        const float* zr = Z + q * 96;
        a0 = fmaf(y, zr[l],      a0);
        a1 = fmaf(y, zr[l + 32], a1);
        a2 = fmaf(y, zr[l + 64], a2);
    }
    ms[l]      = a0 / (1.f + expf(-a0));
    ms[32 + l] = a1 / (1.f + expf(-a1));
    ms[64 + l] = 1.f / (1.f + expf(-a2));
    __syncwarp();

    const float* Zsv = Z + 3072;
    const float* Zvs = Z + 3328;
    #pragma unroll
    for (int cc = 0; cc < 3; cc++) {
        int c = l + cc * 32;
        int w = c / 3, m = c - w * 3;
        float acc = 0.f;
        #pragma unroll
        for (int v = 0; v < 8; v++) {
            acc = fmaf(ye[v],             Zvs[v * 96 + c], acc);
            acc = fmaf(ye[8 + v * 3 + m], Zsv[v * 32 + w], acc);
        }
        mv[c] = acc * ms[64 + w];
    }
    __syncwarp();

    const size_t base = (size_t)row * 192;
    #pragma unroll
    for (int cc = 0; cc < 3; cc++) {
        int w = l + cc * 32;
        float acc = 0.f;
        #pragma unroll 8
        for (int u = 0; u < 64; u++)
            acc = fmaf(ms[u], s_WLs[u * 96 + w], acc);
        atomicAdd(&g_agg[base + w], acc * NORM_LIN64);
    }
    #pragma unroll
    for (int cc = 0; cc < 3; cc++) {
        int c = l + cc * 32;
        int w = c / 3, m = c - w * 3;
        float acc = 0.f;
        #pragma unroll
        for (int u = 0; u < 32; u++)
            acc = fmaf(mv[u * 3 + m], s_WLv[u * 32 + w], acc);
        atomicAdd(&g_agg[base + 96 + c], acc * NORM_LIN32);
    }
}

// ============================================================================
// NODE KERNEL v3: 32 nodes/block, 128 threads, 24 outputs/thread.
// Stage 1: 4n x 6w tiles (A LDS.128 + 3x B LDS.64 per k -> FMA-bound)
// Stage 2: 6r x 4w tiles (3x A LDS.64 + B LDS.128 per k)
// Kc=16, unified double-buffered chunk region, 72KB smem, 3 blocks/SM.
// smem (floats): xsT[64u][32n]@0(2048) xvT[3][32][32]@2048(3072)
//   asT[96][32]@5120(3072) avT[3][32][32]@8192(3072)
//   sCh 2x2048@11264 (st1: A512|B1536, st2: A1536|B512)  s_us[32][96]@15360(3072)
// ============================================================================
#define NODE_SMEM_BYTES (18432 * 4)

__device__ __forceinline__ float4 build1_4(const float* xsT, const float* asT,
                                           const float* xvT, const float* avT,
                                           int k, int n4) {
    float4 r;
    if (k < 6144) {
        int u = k / 96, v = k - u * 96;
        float4 x = *(const float4*)&xsT[u * 32 + n4];
        float4 a = *(const float4*)&asT[v * 32 + n4];
        r.x = x.x * a.x; r.y = x.y * a.y; r.z = x.z * a.z; r.w = x.w * a.w;
    } else {
        int k2 = k - 6144, u = k2 >> 5, v = k2 & 31;
        float sx = 0.f, sy = 0.f, sz = 0.f, sw = 0.f;
        #pragma unroll
        for (int m = 0; m < 3; m++) {
            float4 x = *(const float4*)&xvT[m * 1024 + u * 32 + n4];
            float4 a = *(const float4*)&avT[m * 1024 + v * 32 + n4];
            sx = fmaf(x.x, a.x, sx); sy = fmaf(x.y, a.y, sy);
            sz = fmaf(x.z, a.z, sz); sw = fmaf(x.w, a.w, sw);
        }
        r.x = INV_SQRT3 * sx; r.y = INV_SQRT3 * sy;
        r.z = INV_SQRT3 * sz; r.w = INV_SQRT3 * sw;
    }
    return r;
}

__device__ __forceinline__ void build2_12(const float* xsT, const float* asT,
                                          const float* xvT, const float* avT,
                                          int k, int r0, float* o) {
    if (k < 2048) {
        int u = k >> 5, v = k & 31;
        #pragma unroll
        for (int j = 0; j < 12; j++) {
            int r = r0 + j, m = r >> 5, n = r & 31;
            o[j] = xsT[u * 32 + n] * avT[m * 1024 + v * 32 + n];
        }
    } else {
        int k2 = k - 2048, u = k2 / 96, v = k2 - u * 96;
        #pragma unroll
        for (int j = 0; j < 12; j++) {
            int r = r0 + j, m = r >> 5, n = r & 31;
            o[j] = xvT[m * 1024 + u * 32 + n] * asT[v * 32 + n];
        }
    }
}

__global__ void __launch_bounds__(128, 3) node_kernel(
    const float* __restrict__ nf,
    const float* __restrict__ Wss, const float* __restrict__ Wvv,
    const float* __restrict__ Wsv, const float* __restrict__ Wvs,
    const float* __restrict__ WLs, const float* __restrict__ WLv,
    float* __restrict__ out)
{
    extern __shared__ float sm[];
    float* s_xsT = sm;
    float* s_xvT = sm + 2048;
    float* s_asT = sm + 5120;
    float* s_avT = sm + 8192;
    float* sCh   = sm + 11264;
    float* s_us  = sm + 15360;

    const int t  = threadIdx.x;
    const int n0 = blockIdx.x * 32;

    for (int i = t; i < 32 * 160; i += 128) {
        int n = i / 160, c = i - n * 160;
        int gn = n0 + n;
        float v = (gn < N_NODES) ? nf[(size_t)gn * 160 + c] : 0.f;
        if (c < 64) s_xsT[c * 32 + n] = v;
        else { int c2 = c - 64, u = c2 / 3, m = c2 - u * 3;
               s_xvT[m * 1024 + u * 32 + n] = v; }
    }
    for (int i = t; i < 32 * 192; i += 128) {
        int n = i / 192, c = i - n * 192;
        int gn = n0 + n;
        float v = (gn < N_NODES) ? g_agg[(size_t)gn * 192 + c] : 0.f;
        if (c < 96) s_asT[c * 32 + n] = v;
        else { int c2 = c - 96, w = c2 / 3, m = c2 - w * 3;
               s_avT[m * 1024 + w * 32 + n] = v; }
    }
    __syncthreads();

    // staging maps (128 threads)
    const int kb  = t >> 3;          // k-lane within chunk (16)
    const int n4b = (t & 7) * 4;     // stage1 A: 4 nodes
    const int wB1 = (t & 7) * 12;    // stage1 B: 12 w at row kb
    const int r12 = (t & 7) * 12;    // stage2 A: 12 rows at row kb
    const int w4B = (t & 7) * 4;     // stage2 B: 4 w at row kb

    // ------------------------- stage 1: us, K=7168, 448 chunks -------------
    {
        const int ng = (t & 7) * 4;      // compute: 4 nodes
        const int w6 = (t >> 3) * 6;     // compute: 6 w
        float acc[24];
        #pragma unroll
        for (int i = 0; i < 24; i++) acc[i] = 0.f;

        {   // prologue chunk 0 (k<16: ss region)
            float4 a0 = build1_4(s_xsT, s_asT, s_xvT, s_avT, kb, n4b);
            *(float4*)&sCh[kb * 32 + n4b] = a0;
            const float* src = Wss + (size_t)kb * 96 + wB1;
            *(float4*)&sCh[512 + kb * 96 + wB1    ] = *(const float4*)(src);
            *(float4*)&sCh[512 + kb * 96 + wB1 + 4] = *(const float4*)(src + 4);
            *(float4*)&sCh[512 + kb * 96 + wB1 + 8] = *(const float4*)(src + 8);
        }
        __syncthreads();

        int cur = 0;
        for (int c = 0; c < 448; c++) {
            float4 an, bn0, bn1, bn2;
            const bool pre = (c + 1 < 448);
            if (pre) {
                int kbase = (c + 1) * 16;
                int kw = kbase + kb;
                const float* src = (kw < 6144) ? Wss + (size_t)kw * 96 + wB1
                                               : Wvv + (size_t)(kw - 6144) * 96 + wB1;
                bn0 = *(const float4*)(src);
                bn1 = *(const float4*)(src + 4);
                bn2 = *(const float4*)(src + 8);
                an = build1_4(s_xsT, s_asT, s_xvT, s_avT, kbase + kb, n4b);
            }
            const float* A = sCh + cur * 2048;
            const float* B = A + 512;
            #pragma unroll
            for (int kk = 0; kk < 16; kk++) {
                float4 a  = *(const float4*)&A[kk * 32 + ng];
                float2 b0 = *(const float2*)&B[kk * 96 + w6];
                float2 b1 = *(const float2*)&B[kk * 96 + w6 + 2];
                float2 b2 = *(const float2*)&B[kk * 96 + w6 + 4];
                acc[0]  = fmaf(a.x, b0.x, acc[0]);
                acc[1]  = fmaf(a.x, b0.y, acc[1]);
                acc[2]  = fmaf(a.x, b1.x, acc[2]);
                acc[3]  = fmaf(a.x, b1.y, acc[3]);
                acc[4]  = fmaf(a.x, b2.x, acc[4]);
                acc[5]  = fmaf(a.x, b2.y, acc[5]);
                acc[6]  = fmaf(a.y, b0.x, acc[6]);
                acc[7]  = fmaf(a.y, b0.y, acc[7]);
                acc[8]  = fmaf(a.y, b1.x, acc[8]);
                acc[9]  = fmaf(a.y, b1.y, acc[9]);
                acc[10] = fmaf(a.y, b2.x, acc[10]);
                acc[11] = fmaf(a.y, b2.y, acc[11]);
                acc[12] = fmaf(a.z, b0.x, acc[12]);
                acc[13] = fmaf(a.z, b0.y, acc[13]);
                acc[14] = fmaf(a.z, b1.x, acc[14]);
                acc[15] = fmaf(a.z, b1.y, acc[15]);
                acc[16] = fmaf(a.z, b2.x, acc[16]);
                acc[17] = fmaf(a.z, b2.y, acc[17]);
                acc[18] = fmaf(a.w, b0.x, acc[18]);
                acc[19] = fmaf(a.w, b0.y, acc[19]);
                acc[20] = fmaf(a.w, b1.x, acc[20]);
                acc[21] = fmaf(a.w, b1.y, acc[21]);
                acc[22] = fmaf(a.w, b2.x, acc[22]);
                acc[23] = fmaf(a.w, b2.y, acc[23]);
            }
            if (pre) {
                float* An = sCh + (cur ^ 1) * 2048;
                float* Bn = An + 512;
                *(float4*)&An[kb * 32 + n4b] = an;
                *(float4*)&Bn[kb * 96 + wB1    ] = bn0;
                *(float4*)&Bn[kb * 96 + wB1 + 4] = bn1;
                *(float4*)&Bn[kb * 96 + wB1 + 8] = bn2;
            }
            __syncthreads();
            cur ^= 1;
        }
        #pragma unroll
        for (int i = 0; i < 4; i++)
            #pragma unroll
            for (int j = 0; j < 6; j++)
                s_us[(ng + i) * 96 + w6 + j] = acc[i * 6 + j] * NORM_UPD_S;
    }

    // ------------------------- stage 2: uv, K=5120, 320 chunks -------------
    {
        const int w4c = (t & 7) * 4;     // compute: 4 w
        const int r6  = (t >> 3) * 6;    // compute: 6 rows
        float acc2[24];
        #pragma unroll
        for (int i = 0; i < 24; i++) acc2[i] = 0.f;

        {   // prologue chunk 0 (k<16: sv region)
            float o[12];
            build2_12(s_xsT, s_asT, s_xvT, s_avT, kb, r12, o);
            #pragma unroll
            for (int j = 0; j < 12; j += 4)
                *(float4*)&sCh[kb * 96 + r12 + j] = *(float4*)&o[j];
            *(float4*)&sCh[1536 + kb * 32 + w4B] =
                *(const float4*)(Wsv + (size_t)kb * 32 + w4B);
        }
        __syncthreads();

        int cur = 0;
        for (int c = 0; c < 320; c++) {
            float on[12];
            float4 bn;
            const bool pre = (c + 1 < 320);
            if (pre) {
                int kbase = (c + 1) * 16;
                int kw = kbase + kb;
                const float* src = (kw < 2048) ? Wsv + (size_t)kw * 32 + w4B
                                               : Wvs + (size_t)(kw - 2048) * 32 + w4B;
                bn = *(const float4*)src;
                build2_12(s_xsT, s_asT, s_xvT, s_avT, kbase + kb, r12, on);
            }
            const float* A = sCh + cur * 2048;
            const float* B = A + 1536;
            #pragma unroll
            for (int kk = 0; kk < 16; kk++) {
                float2 a01 = *(const float2*)&A[kk * 96 + r6];
                float2 a23 = *(const float2*)&A[kk * 96 + r6 + 2];
                float2 a45 = *(const float2*)&A[kk * 96 + r6 + 4];
                float4 b   = *(const float4*)&B[kk * 32 + w4c];
                acc2[0]  = fmaf(a01.x, b.x, acc2[0]);
                acc2[1]  = fmaf(a01.x, b.y, acc2[1]);
                acc2[2]  = fmaf(a01.x, b.z, acc2[2]);
                acc2[3]  = fmaf(a01.x, b.w, acc2[3]);
                acc2[4]  = fmaf(a01.y, b.x, acc2[4]);
                acc2[5]  = fmaf(a01.y, b.y, acc2[5]);
                acc2[6]  = fmaf(a01.y, b.z, acc2[6]);
                acc2[7]  = fmaf(a01.y, b.w, acc2[7]);
                acc2[8]  = fmaf(a23.x, b.x, acc2[8]);
                acc2[9]  = fmaf(a23.x, b.y, acc2[9]);
                acc2[10] = fmaf(a23.x, b.z, acc2[10]);
                acc2[11] = fmaf(a23.x, b.w, acc2[11]);
                acc2[12] = fmaf(a23.y, b.x, acc2[12]);
                acc2[13] = fmaf(a23.y, b.y, acc2[13]);
                acc2[14] = fmaf(a23.y, b.z, acc2[14]);
                acc2[15] = fmaf(a23.y, b.w, acc2[15]);
                acc2[16] = fmaf(a45.x, b.x, acc2[16]);
                acc2[17] = fmaf(a45.x, b.y, acc2[17]);
                acc2[18] = fmaf(a45.x, b.z, acc2[18]);
                acc2[19] = fmaf(a45.x, b.w, acc2[19]);
                acc2[20] = fmaf(a45.y, b.x, acc2[20]);
                acc2[21] = fmaf(a45.y, b.y, acc2[21]);
                acc2[22] = fmaf(a45.y, b.z, acc2[22]);
                acc2[23] = fmaf(a45.y, b.w, acc2[23]);
            }
            if (pre) {
                float* An = sCh + (cur ^ 1) * 2048;
                float* Bn = An + 1536;
                #pragma unroll
                for (int j = 0; j < 12; j += 4)
                    *(float4*)&An[kb * 96 + r12 + j] = *(float4*)&on[j];
                *(float4*)&Bn[kb * 32 + w4B] = bn;
            }
            __syncthreads();
            cur ^= 1;
        }
        // store uv TRANSPOSED: s_uvT[w<32][r<96] into sCh (buffers dead)
        float* s_uvT = sCh;
        #pragma unroll
        for (int jw = 0; jw < 4; jw++)
            #pragma unroll
            for (int ir = 0; ir < 6; ir++)
                s_uvT[(w4c + jw) * 96 + r6 + ir] = acc2[ir * 4 + jw] * NORM_UPD_V;
    }

    // ------------------------- epilogue -------------------------
    float* s_uvT = sCh;            // [w<32][r=m*32+n]
    float* s_gT  = sCh + 3072;     // [w<32][n<32]
    float* s_WL  = s_asT;          // WLs 4096 (asT+avT dead)
    float* s_WLv = s_asT + 4096;   // WLv 1024

    for (int i = t; i < 4096; i += 128) s_WL[i] = WLs[i];
    for (int i = t; i < 1024; i += 128) s_WLv[i] = WLv[i];
    for (int i = t; i < 2048; i += 128) {
        int n = i >> 6, u = i & 63;
        float x = s_us[n * 96 + u];
        s_us[n * 96 + u] = x / (1.f + expf(-x));
    }
    for (int i = t; i < 1024; i += 128) {
        int w = i >> 5, n = i & 31;
        s_gT[i] = 1.f / (1.f + expf(-s_us[n * 96 + 64 + w]));
    }
    __syncthreads();
    for (int i = t; i < 3072; i += 128) {
        int w = i / 96, r = i - w * 96;
        s_uvT[i] *= s_gT[w * 32 + (r & 31)];
    }
    __syncthreads();

    for (int i = t; i < 2048; i += 128) {
        int n = i >> 6, w = i & 63;
        int gn = n0 + n;
        if (gn < N_NODES) {
            float s = 0.f;
            #pragma unroll 8
            for (int u = 0; u < 64; u++)
                s = fmaf(s_us[n * 96 + u], s_WL[u * 64 + w], s);
            out[(size_t)gn * 160 + w] = nf[(size_t)gn * 160 + w] + s * NORM_LIN64;
        }
    }
    for (int i = t; i < 3072; i += 128) {
        int n = i / 96, c = i - n * 96;
        int w = c / 3, m = c - w * 3;
        int gn = n0 + n;
        if (gn < N_NODES) {
            float s = 0.f;
            #pragma unroll
            for (int u = 0; u < 32; u++)
                s = fmaf(s_uvT[u * 96 + m * 32 + n], s_WLv[u * 32 + w], s);
            out[(size_t)gn * 160 + 64 + c] = nf[(size_t)gn * 160 + 64 + c] + s * NORM_LIN32;
        }
    }
}

extern "C" void kernel_launch(void* const* d_in, const int* in_sizes, int n_in,
                              void* d_out, int out_size) {
    const float* nf   = (const float*)d_in[0];
    const float* ea   = (const float*)d_in[1];
    const float* Wmss = (const float*)d_in[2];
    const float* Wmvv = (const float*)d_in[3];
    const float* Wmsv = (const float*)d_in[4];
    const float* Wmvs = (const float*)d_in[5];
    const float* WLms = (const float*)d_in[6];
    const float* WLmv = (const float*)d_in[7];
    const float* Wuss = (const float*)d_in[8];
    const float* Wuvv = (const float*)d_in[9];
    const float* Wusv = (const float*)d_in[10];
    const float* Wuvs = (const float*)d_in[11];
    const float* WLus = (const float*)d_in[12];
    const float* WLuv = (const float*)d_in[13];
    const int*   eidx = (const int*)d_in[14];
    float* out = (float*)d_out;

    cudaFuncSetAttribute(node_kernel, cudaFuncAttributeMaxDynamicSharedMemorySize,
                         NODE_SMEM_BYTES);
    cudaFuncSetAttribute(node_kernel, cudaFuncAttributePreferredSharedMemoryCarveout,
                         100);

    zero_agg_kernel<<<(N_NODES * 192 + 255) / 256, 256>>>();
    precompute_z<<<(N_NODES + 31) / 32, 256>>>(nf, Wmss, Wmvv, Wmsv, Wmvs);
    edge_kernel<<<N_EDGES / EB, 256>>>(ea, WLms, WLmv, eidx);
    node_kernel<<<(N_NODES + 31) / 32, 128, NODE_SMEM_BYTES>>>(
        nf, Wuss, Wuvv, Wusv, Wuvs, WLus, WLuv, out);
}

// round 9
// speedup vs baseline: 8.3161x; 1.0477x over previous
#include <cuda_runtime.h>
#include <math.h>

#define N_NODES 10000
#define N_EDGES 100000

#define INV_SQRT3    0.57735026918962576f
#define NORM_MSG     0.036084391824351614f   // 1/sqrt(768)
#define NORM_MSG_V3  (0.036084391824351614f * 0.57735026918962576f)
#define NORM_UPD_S   0.011811391307201575f   // 1/sqrt(7168)
#define NORM_UPD_V   0.013975424859373686f   // 1/sqrt(5120)
#define NORM_LIN64   0.125f                  // 1/sqrt(64)
#define NORM_LIN32   0.17677669529663687f    // 1/sqrt(32)

#define ZSTRIDE 4096
// per-node factored message tensor product (norms folded in):
// [0,768) Zss[v<8][w<96], [768,3072) Zvv[(v*3+m)<24][w<96],
// [3072,3328) Zsv[v<8][w<32], [3328,4096) Zvs[v<8][(w*3+m)<96]
__device__ float g_z[(size_t)N_NODES * ZSTRIDE];
__device__ float g_agg[N_NODES * 192];   // [96 scalars | 32x3 vectors] per node
__device__ float g_upd[N_NODES * 192];   // raw partial sums: us[96] | uv[u*3+m]

__global__ void zero_kernel() {
    int i = blockIdx.x * blockDim.x + threadIdx.x;
    if (i < N_NODES * 192) { g_agg[i] = 0.f; g_upd[i] = 0.f; }
}

// ============================================================================
// Z PRECOMPUTE: 32 nodes/block, 256 threads.  (unchanged)
// ============================================================================
__global__ void __launch_bounds__(256) precompute_z(
    const float* __restrict__ nf,
    const float* __restrict__ Wss, const float* __restrict__ Wvv,
    const float* __restrict__ Wsv, const float* __restrict__ Wvs)
{
    __shared__ float s_xs[32 * 64];
    __shared__ float s_xv[32 * 96];
    const int t = threadIdx.x;
    const int n0 = blockIdx.x * 32;

    for (int i = t; i < 32 * 160; i += 256) {
        int n = i / 160, c = i - n * 160;
        int gn = n0 + n;
        float v = (gn < N_NODES) ? nf[(size_t)gn * 160 + c] : 0.f;
        if (c < 64) s_xs[n * 64 + c] = v; else s_xv[n * 96 + (c - 64)] = v;
    }
    __syncthreads();

    const int ng = t >> 6;
    const int c0 = t & 63;

    for (int c = c0; c < 768; c += 64) {
        float acc[8] = {0,0,0,0,0,0,0,0};
        #pragma unroll 8
        for (int u = 0; u < 64; u++) {
            float b = Wss[u * 768 + c];
            #pragma unroll
            for (int j = 0; j < 8; j++)
                acc[j] = fmaf(s_xs[(ng * 8 + j) * 64 + u], b, acc[j]);
        }
        #pragma unroll
        for (int j = 0; j < 8; j++) {
            int gn = n0 + ng * 8 + j;
            if (gn < N_NODES) g_z[(size_t)gn * ZSTRIDE + c] = acc[j] * NORM_MSG;
        }
    }
    for (int c = c0; c < 2304; c += 64) {
        int v = c / 288, rem = c - v * 288;
        int m = rem / 96, w = rem - m * 96;
        float acc[8] = {0,0,0,0,0,0,0,0};
        #pragma unroll 8
        for (int u = 0; u < 32; u++) {
            float b = Wvv[u * 768 + v * 96 + w];
            #pragma unroll
            for (int j = 0; j < 8; j++)
                acc[j] = fmaf(s_xv[(ng * 8 + j) * 96 + u * 3 + m], b, acc[j]);
        }
        #pragma unroll
        for (int j = 0; j < 8; j++) {
            int gn = n0 + ng * 8 + j;
            if (gn < N_NODES) g_z[(size_t)gn * ZSTRIDE + 768 + c] = acc[j] * NORM_MSG_V3;
        }
    }
    for (int c = c0; c < 256; c += 64) {
        float acc[8] = {0,0,0,0,0,0,0,0};
        #pragma unroll 8
        for (int u = 0; u < 64; u++) {
            float b = Wsv[u * 256 + c];
            #pragma unroll
            for (int j = 0; j < 8; j++)
                acc[j] = fmaf(s_xs[(ng * 8 + j) * 64 + u], b, acc[j]);
        }
        #pragma unroll
        for (int j = 0; j < 8; j++) {
            int gn = n0 + ng * 8 + j;
            if (gn < N_NODES) g_z[(size_t)gn * ZSTRIDE + 3072 + c] = acc[j] * NORM_MSG;
        }
    }
    for (int c = c0; c < 768; c += 64) {
        int v = c / 96, rem = c - v * 96;
        int w = rem / 3, m = rem - w * 3;
        float acc[8] = {0,0,0,0,0,0,0,0};
        #pragma unroll 8
        for (int u = 0; u < 32; u++) {
            float b = Wvs[u * 256 + v * 32 + w];
            #pragma unroll
            for (int j = 0; j < 8; j++)
                acc[j] = fmaf(s_xv[(ng * 8 + j) * 96 + u * 3 + m], b, acc[j]);
        }
        #pragma unroll
        for (int j = 0; j < 8; j++) {
            int gn = n0 + ng * 8 + j;
            if (gn < N_NODES) g_z[(size_t)gn * ZSTRIDE + 3328 + c] = acc[j] * NORM_MSG;
        }
    }
}

// ============================================================================
// EDGE KERNEL: warp-per-edge, 8 edges / 256-thread block.  (unchanged)
// ============================================================================
#define EB 8
__global__ void __launch_bounds__(256) edge_kernel(
    const float* __restrict__ ea,
    const float* __restrict__ WLs, const float* __restrict__ WLv,
    const int* __restrict__ eidx)
{
    __shared__ float s_WLs[64 * 96];
    __shared__ float s_WLv[32 * 32];
    __shared__ float s_y [EB * 32];
    __shared__ float s_ms[EB * 96];
    __shared__ float s_mv[EB * 96];

    const int t = threadIdx.x;
    for (int i = t; i < 6144; i += 256) s_WLs[i] = WLs[i];
    for (int i = t; i < 1024; i += 256) s_WLv[i] = WLv[i];

    const int es = t >> 5, l = t & 31;
    const int e = blockIdx.x * EB + es;
    s_y[es * 32 + l] = ea[(size_t)e * 32 + l];
    __syncthreads();

    const int row = eidx[e];
    const int col = eidx[N_EDGES + e];
    const float* Z  = g_z + (size_t)col * ZSTRIDE;
    const float* ye = s_y + es * 32;
    float* ms = s_ms + es * 96;
    float* mv = s_mv + es * 96;

    float a0 = 0.f, a1 = 0.f, a2 = 0.f;
    #pragma unroll 8
    for (int q = 0; q < 32; q++) {
        float y = ye[q];
        const float* zr = Z + q * 96;
        a0 = fmaf(y, zr[l],      a0);
        a1 = fmaf(y, zr[l + 32], a1);
        a2 = fmaf(y, zr[l + 64], a2);
    }
    ms[l]      = a0 / (1.f + expf(-a0));
    ms[32 + l] = a1 / (1.f + expf(-a1));
    ms[64 + l] = 1.f / (1.f + expf(-a2));
    __syncwarp();

    const float* Zsv = Z + 3072;
    const float* Zvs = Z + 3328;
    #pragma unroll
    for (int cc = 0; cc < 3; cc++) {
        int c = l + cc * 32;
        int w = c / 3, m = c - w * 3;
        float acc = 0.f;
        #pragma unroll
        for (int v = 0; v < 8; v++) {
            acc = fmaf(ye[v],             Zvs[v * 96 + c], acc);
            acc = fmaf(ye[8 + v * 3 + m], Zsv[v * 32 + w], acc);
        }
        mv[c] = acc * ms[64 + w];
    }
    __syncwarp();

    const size_t base = (size_t)row * 192;
    #pragma unroll
    for (int cc = 0; cc < 3; cc++) {
        int w = l + cc * 32;
        float acc = 0.f;
        #pragma unroll 8
        for (int u = 0; u < 64; u++)
            acc = fmaf(ms[u], s_WLs[u * 96 + w], acc);
        atomicAdd(&g_agg[base + w], acc * NORM_LIN64);
    }
    #pragma unroll
    for (int cc = 0; cc < 3; cc++) {
        int c = l + cc * 32;
        int w = c / 3, m = c - w * 3;
        float acc = 0.f;
        #pragma unroll
        for (int u = 0; u < 32; u++)
            acc = fmaf(mv[u * 3 + m], s_WLv[u * 32 + w], acc);
        atomicAdd(&g_agg[base + 96 + c], acc * NORM_LIN32);
    }
}

// ============================================================================
// NODE KERNEL v4: 2-way K-split. grid = 626 (tile = bx>>1, khalf = bx&1).
// 128 threads, 32 nodes/tile, Kc=8, 53KB smem -> 4 blocks/SM (16 warps).
// Raw partial sums -> atomicAdd g_upd. Epilogue kernel finishes.
// smem (floats): xsT[64][32]@0  xvT[3][32][32]@2048  asT[96][32]@5120
//   avT[3][32][32]@8192  sCh 2x1024@11264
// ============================================================================
#define NODE_SMEM_BYTES (13312 * 4)

__device__ __forceinline__ float2 build1_2(const float* xsT, const float* asT,
                                           const float* xvT, const float* avT,
                                           int k, int n2) {
    float2 r;
    if (k < 6144) {
        int u = k / 96, v = k - u * 96;
        float2 x = *(const float2*)&xsT[u * 32 + n2];
        float2 a = *(const float2*)&asT[v * 32 + n2];
        r.x = x.x * a.x; r.y = x.y * a.y;
    } else {
        int k2 = k - 6144, u = k2 >> 5, v = k2 & 31;
        float sx = 0.f, sy = 0.f;
        #pragma unroll
        for (int m = 0; m < 3; m++) {
            float2 x = *(const float2*)&xvT[m * 1024 + u * 32 + n2];
            float2 a = *(const float2*)&avT[m * 1024 + v * 32 + n2];
            sx = fmaf(x.x, a.x, sx); sy = fmaf(x.y, a.y, sy);
        }
        r.x = INV_SQRT3 * sx; r.y = INV_SQRT3 * sy;
    }
    return r;
}

__device__ __forceinline__ void build2_6(const float* xsT, const float* asT,
                                         const float* xvT, const float* avT,
                                         int k, int r0, float* o) {
    if (k < 2048) {
        int u = k >> 5, v = k & 31;
        #pragma unroll
        for (int j = 0; j < 6; j++) {
            int r = r0 + j, m = r >> 5, n = r & 31;
            o[j] = xsT[u * 32 + n] * avT[m * 1024 + v * 32 + n];
        }
    } else {
        int k2 = k - 2048, u = k2 / 96, v = k2 - u * 96;
        #pragma unroll
        for (int j = 0; j < 6; j++) {
            int r = r0 + j, m = r >> 5, n = r & 31;
            o[j] = xvT[m * 1024 + u * 32 + n] * asT[v * 32 + n];
        }
    }
}

__global__ void __launch_bounds__(128, 4) node_kernel(
    const float* __restrict__ nf,
    const float* __restrict__ Wss, const float* __restrict__ Wvv,
    const float* __restrict__ Wsv, const float* __restrict__ Wvs)
{
    extern __shared__ float sm[];
    float* s_xsT = sm;
    float* s_xvT = sm + 2048;
    float* s_asT = sm + 5120;
    float* s_avT = sm + 8192;
    float* sCh   = sm + 11264;   // 2 x 1024

    const int t    = threadIdx.x;
    const int tile = blockIdx.x >> 1;
    const int half = blockIdx.x & 1;
    const int n0   = tile * 32;

    for (int i = t; i < 32 * 160; i += 128) {
        int n = i / 160, c = i - n * 160;
        int gn = n0 + n;
        float v = (gn < N_NODES) ? nf[(size_t)gn * 160 + c] : 0.f;
        if (c < 64) s_xsT[c * 32 + n] = v;
        else { int c2 = c - 64, u = c2 / 3, m = c2 - u * 3;
               s_xvT[m * 1024 + u * 32 + n] = v; }
    }
    for (int i = t; i < 32 * 192; i += 128) {
        int n = i / 192, c = i - n * 192;
        int gn = n0 + n;
        float v = (gn < N_NODES) ? g_agg[(size_t)gn * 192 + c] : 0.f;
        if (c < 96) s_asT[c * 32 + n] = v;
        else { int c2 = c - 96, w = c2 / 3, m = c2 - w * 3;
               s_avT[m * 1024 + w * 32 + n] = v; }
    }
    __syncthreads();

    const int kb  = t >> 4;          // chunk k-row (8)
    const int n2b = (t & 15) * 2;    // stage1 A staging: 2 nodes
    const int wB6 = (t & 15) * 6;    // stage1 B staging: 6 w
    const int r6b = (t & 15) * 6;    // stage2 A staging: 6 rows
    const int w2B = (t & 15) * 2;    // stage2 B staging: 2 w

    // ---------------- stage 1: us partial, 448 chunks of 8 ----------------
    {
        const int k_off = half * 3584;
        const int ng = (t & 7) * 4;
        const int w6 = (t >> 3) * 6;
        float acc[24];
        #pragma unroll
        for (int i = 0; i < 24; i++) acc[i] = 0.f;

        {   // prologue
            int kw = k_off + kb;
            float2 a0 = build1_2(s_xsT, s_asT, s_xvT, s_avT, kw, n2b);
            *(float2*)&sCh[kb * 32 + n2b] = a0;
            const float* src = (kw < 6144) ? Wss + (size_t)kw * 96 + wB6
                                           : Wvv + (size_t)(kw - 6144) * 96 + wB6;
            *(float2*)&sCh[256 + kb * 96 + wB6    ] = *(const float2*)(src);
            *(float2*)&sCh[256 + kb * 96 + wB6 + 2] = *(const float2*)(src + 2);
            *(float2*)&sCh[256 + kb * 96 + wB6 + 4] = *(const float2*)(src + 4);
        }
        __syncthreads();

        int cur = 0;
        for (int c = 0; c < 448; c++) {
            float2 an, bn0, bn1, bn2;
            const bool pre = (c + 1 < 448);
            if (pre) {
                int kw = k_off + (c + 1) * 8 + kb;
                const float* src = (kw < 6144) ? Wss + (size_t)kw * 96 + wB6
                                               : Wvv + (size_t)(kw - 6144) * 96 + wB6;
                bn0 = *(const float2*)(src);
                bn1 = *(const float2*)(src + 2);
                bn2 = *(const float2*)(src + 4);
                an = build1_2(s_xsT, s_asT, s_xvT, s_avT, kw, n2b);
            }
            const float* A = sCh + cur * 1024;
            const float* B = A + 256;
            #pragma unroll
            for (int kk = 0; kk < 8; kk++) {
                float4 a  = *(const float4*)&A[kk * 32 + ng];
                float2 b0 = *(const float2*)&B[kk * 96 + w6];
                float2 b1 = *(const float2*)&B[kk * 96 + w6 + 2];
                float2 b2 = *(const float2*)&B[kk * 96 + w6 + 4];
                acc[0]  = fmaf(a.x, b0.x, acc[0]);
                acc[1]  = fmaf(a.x, b0.y, acc[1]);
                acc[2]  = fmaf(a.x, b1.x, acc[2]);
                acc[3]  = fmaf(a.x, b1.y, acc[3]);
                acc[4]  = fmaf(a.x, b2.x, acc[4]);
                acc[5]  = fmaf(a.x, b2.y, acc[5]);
                acc[6]  = fmaf(a.y, b0.x, acc[6]);
                acc[7]  = fmaf(a.y, b0.y, acc[7]);
                acc[8]  = fmaf(a.y, b1.x, acc[8]);
                acc[9]  = fmaf(a.y, b1.y, acc[9]);
                acc[10] = fmaf(a.y, b2.x, acc[10]);
                acc[11] = fmaf(a.y, b2.y, acc[11]);
                acc[12] = fmaf(a.z, b0.x, acc[12]);
                acc[13] = fmaf(a.z, b0.y, acc[13]);
                acc[14] = fmaf(a.z, b1.x, acc[14]);
                acc[15] = fmaf(a.z, b1.y, acc[15]);
                acc[16] = fmaf(a.z, b2.x, acc[16]);
                acc[17] = fmaf(a.z, b2.y, acc[17]);
                acc[18] = fmaf(a.w, b0.x, acc[18]);
                acc[19] = fmaf(a.w, b0.y, acc[19]);
                acc[20] = fmaf(a.w, b1.x, acc[20]);
                acc[21] = fmaf(a.w, b1.y, acc[21]);
                acc[22] = fmaf(a.w, b2.x, acc[22]);
                acc[23] = fmaf(a.w, b2.y, acc[23]);
            }
            if (pre) {
                float* An = sCh + (cur ^ 1) * 1024;
                float* Bn = An + 256;
                *(float2*)&An[kb * 32 + n2b] = an;
                *(float2*)&Bn[kb * 96 + wB6    ] = bn0;
                *(float2*)&Bn[kb * 96 + wB6 + 2] = bn1;
                *(float2*)&Bn[kb * 96 + wB6 + 4] = bn2;
            }
            __syncthreads();
            cur ^= 1;
        }
        #pragma unroll
        for (int i = 0; i < 4; i++) {
            int gn = n0 + ng + i;
            if (gn < N_NODES) {
                #pragma unroll
                for (int j = 0; j < 6; j++)
                    atomicAdd(&g_upd[(size_t)gn * 192 + w6 + j], acc[i * 6 + j]);
            }
        }
    }
    __syncthreads();

    // ---------------- stage 2: uv partial, 320 chunks of 8 ----------------
    {
        const int k_off = half * 2560;
        const int w4 = (t & 7) * 4;
        const int r6 = (t >> 3) * 6;
        float acc[24];
        #pragma unroll
        for (int i = 0; i < 24; i++) acc[i] = 0.f;

        {   // prologue
            int kw = k_off + kb;
            float o[6];
            build2_6(s_xsT, s_asT, s_xvT, s_avT, kw, r6b, o);
            *(float2*)&sCh[kb * 96 + r6b    ] = *(float2*)&o[0];
            *(float2*)&sCh[kb * 96 + r6b + 2] = *(float2*)&o[2];
            *(float2*)&sCh[kb * 96 + r6b + 4] = *(float2*)&o[4];
            const float* src = (kw < 2048) ? Wsv + (size_t)kw * 32 + w2B
                                           : Wvs + (size_t)(kw - 2048) * 32 + w2B;
            *(float2*)&sCh[768 + kb * 32 + w2B] = *(const float2*)src;
        }
        __syncthreads();

        int cur = 0;
        for (int c = 0; c < 320; c++) {
            float on[6];
            float2 bn;
            const bool pre = (c + 1 < 320);
            if (pre) {
                int kw = k_off + (c + 1) * 8 + kb;
                const float* src = (kw < 2048) ? Wsv + (size_t)kw * 32 + w2B
                                               : Wvs + (size_t)(kw - 2048) * 32 + w2B;
                bn = *(const float2*)src;
                build2_6(s_xsT, s_asT, s_xvT, s_avT, kw, r6b, on);
            }
            const float* A = sCh + cur * 1024;
            const float* B = A + 768;
            #pragma unroll
            for (int kk = 0; kk < 8; kk++) {
                float2 a01 = *(const float2*)&A[kk * 96 + r6];
                float2 a23 = *(const float2*)&A[kk * 96 + r6 + 2];
                float2 a45 = *(const float2*)&A[kk * 96 + r6 + 4];
                float4 b   = *(const float4*)&B[kk * 32 + w4];
                acc[0]  = fmaf(a01.x, b.x, acc[0]);
                acc[1]  = fmaf(a01.x, b.y, acc[1]);
                acc[2]  = fmaf(a01.x, b.z, acc[2]);
                acc[3]  = fmaf(a01.x, b.w, acc[3]);
                acc[4]  = fmaf(a01.y, b.x, acc[4]);
                acc[5]  = fmaf(a01.y, b.y, acc[5]);
                acc[6]  = fmaf(a01.y, b.z, acc[6]);
                acc[7]  = fmaf(a01.y, b.w, acc[7]);
                acc[8]  = fmaf(a23.x, b.x, acc[8]);
                acc[9]  = fmaf(a23.x, b.y, acc[9]);
                acc[10] = fmaf(a23.x, b.z, acc[10]);
                acc[11] = fmaf(a23.x, b.w, acc[11]);
                acc[12] = fmaf(a23.y, b.x, acc[12]);
                acc[13] = fmaf(a23.y, b.y, acc[13]);
                acc[14] = fmaf(a23.y, b.z, acc[14]);
                acc[15] = fmaf(a23.y, b.w, acc[15]);
                acc[16] = fmaf(a45.x, b.x, acc[16]);
                acc[17] = fmaf(a45.x, b.y, acc[17]);
                acc[18] = fmaf(a45.x, b.z, acc[18]);
                acc[19] = fmaf(a45.x, b.w, acc[19]);
                acc[20] = fmaf(a45.y, b.x, acc[20]);
                acc[21] = fmaf(a45.y, b.y, acc[21]);
                acc[22] = fmaf(a45.y, b.z, acc[22]);
                acc[23] = fmaf(a45.y, b.w, acc[23]);
            }
            if (pre) {
                float* An = sCh + (cur ^ 1) * 1024;
                float* Bn = An + 768;
                *(float2*)&An[kb * 96 + r6b    ] = *(float2*)&on[0];
                *(float2*)&An[kb * 96 + r6b + 2] = *(float2*)&on[2];
                *(float2*)&An[kb * 96 + r6b + 4] = *(float2*)&on[4];
                *(float2*)&Bn[kb * 32 + w2B] = bn;
            }
            __syncthreads();
            cur ^= 1;
        }
        #pragma unroll
        for (int i = 0; i < 6; i++) {
            int r = r6 + i, m = r >> 5, n = r & 31;
            int gn = n0 + n;
            if (gn < N_NODES) {
                #pragma unroll
                for (int j = 0; j < 4; j++)
                    atomicAdd(&g_upd[(size_t)gn * 192 + 96 + (w4 + j) * 3 + m],
                              acc[i * 4 + j]);
            }
        }
    }
}

// ============================================================================
// EPILOGUE: norm + gate + linear + residual. 32 nodes/block, 128 threads.
// ============================================================================
__global__ void __launch_bounds__(128) epilogue_kernel(
    const float* __restrict__ nf,
    const float* __restrict__ WLs, const float* __restrict__ WLv,
    float* __restrict__ out)
{
    __shared__ float s_WLs[4096];
    __shared__ float s_WLv[1024];
    __shared__ float s_us[3072];
    __shared__ float s_uv[3072];

    const int t  = threadIdx.x;
    const int n0 = blockIdx.x * 32;

    for (int i = t; i < 4096; i += 128) s_WLs[i] = WLs[i];
    for (int i = t; i < 1024; i += 128) s_WLv[i] = WLv[i];
    for (int i = t; i < 3072; i += 128) {
        int n = i / 96, c = i - n * 96;
        int gn = n0 + n;
        float us = 0.f, uv = 0.f;
        if (gn < N_NODES) {
            us = g_upd[(size_t)gn * 192 + c];
            uv = g_upd[(size_t)gn * 192 + 96 + c];
        }
        s_us[i] = us; s_uv[i] = uv;
    }
    __syncthreads();

    for (int i = t; i < 2048; i += 128) {
        int n = i >> 6, u = i & 63;
        float x = s_us[n * 96 + u] * NORM_UPD_S;
        s_us[n * 96 + u] = x / (1.f + expf(-x));
    }
    for (int i = t; i < 1024; i += 128) {
        int n = i >> 5, w = i & 31;
        float x = s_us[n * 96 + 64 + w] * NORM_UPD_S;
        s_us[n * 96 + 64 + w] = 1.f / (1.f + expf(-x));
    }
    __syncthreads();
    for (int i = t; i < 3072; i += 128) {
        int n = i / 96, c = i - n * 96;
        int u = c / 3;
        s_uv[i] = s_uv[i] * NORM_UPD_V * s_us[n * 96 + 64 + u];
    }
    __syncthreads();

    for (int i = t; i < 2048; i += 128) {
        int n = i >> 6, w = i & 63;
        int gn = n0 + n;
        if (gn < N_NODES) {
            float s = 0.f;
            #pragma unroll 8
            for (int u = 0; u < 64; u++)
                s = fmaf(s_us[n * 96 + u], s_WLs[u * 64 + w], s);
            out[(size_t)gn * 160 + w] = nf[(size_t)gn * 160 + w] + s * NORM_LIN64;
        }
    }
    for (int i = t; i < 3072; i += 128) {
        int n = i / 96, c = i - n * 96;
        int w = c / 3, m = c - w * 3;
        int gn = n0 + n;
        if (gn < N_NODES) {
            float s = 0.f;
            #pragma unroll
            for (int u = 0; u < 32; u++)
                s = fmaf(s_uv[n * 96 + u * 3 + m], s_WLv[u * 32 + w], s);
            out[(size_t)gn * 160 + 64 + c] = nf[(size_t)gn * 160 + 64 + c] + s * NORM_LIN32;
        }
    }
}

extern "C" void kernel_launch(void* const* d_in, const int* in_sizes, int n_in,
                              void* d_out, int out_size) {
    const float* nf   = (const float*)d_in[0];
    const float* ea   = (const float*)d_in[1];
    const float* Wmss = (const float*)d_in[2];
    const float* Wmvv = (const float*)d_in[3];
    const float* Wmsv = (const float*)d_in[4];
    const float* Wmvs = (const float*)d_in[5];
    const float* WLms = (const float*)d_in[6];
    const float* WLmv = (const float*)d_in[7];
    const float* Wuss = (const float*)d_in[8];
    const float* Wuvv = (const float*)d_in[9];
    const float* Wusv = (const float*)d_in[10];
    const float* Wuvs = (const float*)d_in[11];
    const float* WLus = (const float*)d_in[12];
    const float* WLuv = (const float*)d_in[13];
    const int*   eidx = (const int*)d_in[14];
    float* out = (float*)d_out;

    cudaFuncSetAttribute(node_kernel, cudaFuncAttributeMaxDynamicSharedMemorySize,
                         NODE_SMEM_BYTES);
    cudaFuncSetAttribute(node_kernel, cudaFuncAttributePreferredSharedMemoryCarveout,
                         100);

    zero_kernel<<<(N_NODES * 192 + 255) / 256, 256>>>();
    precompute_z<<<(N_NODES + 31) / 32, 256>>>(nf, Wmss, Wmvv, Wmsv, Wmvs);
    edge_kernel<<<N_EDGES / EB, 256>>>(ea, WLms, WLmv, eidx);
    node_kernel<<<2 * ((N_NODES + 31) / 32), 128, NODE_SMEM_BYTES>>>(
        nf, Wuss, Wuvv, Wusv, Wuvs);
    epilogue_kernel<<<(N_NODES + 31) / 32, 128>>>(nf, WLus, WLuv, out);
}